// round 4
// baseline (speedup 1.0000x reference)
#include <cuda_runtime.h>
#include <math.h>

#define T_LEN  2048
#define BATCH  4
#define DMODEL 1024
#define NHEAD  16
#define HDIM   64
#define MROWS  (T_LEN * BATCH)   // 8192

// Scratch buffers ( __device__ globals: no allocation allowed )
__device__ float g_Q[(size_t)BATCH * NHEAD * T_LEN * HDIM];
__device__ float g_K[(size_t)BATCH * NHEAD * T_LEN * HDIM];
__device__ float g_V[(size_t)BATCH * NHEAD * T_LEN * HDIM];
__device__ float g_ctx[(size_t)MROWS * DMODEL];

// ---------------------------------------------------------------------------
// GEMM: y = x @ W^T + bias      (x: [M,K] row-major, W: [N,K] row-major)
// MODE 0/1/2 : QKV projection, scatter into [B,H,T,HD] (g_Q/g_K/g_V)
// MODE 3     : output projection, x = g_ctx, out = (y) * time_decay
// Tiling: 128x128x8, 256 threads, 8x8 micro-tile per thread.
// ---------------------------------------------------------------------------
template <int MODE>
__global__ void __launch_bounds__(256)
gemm_kernel(const float* __restrict__ x,
            const float* __restrict__ W,
            const float* __restrict__ bias,
            float* __restrict__ out,
            const float* __restrict__ tdecay)
{
    __shared__ float As[8][128];
    __shared__ float Bs[8][128];

    const int tid = threadIdx.x;
    const int m0  = blockIdx.y * 128;
    const int n0  = blockIdx.x * 128;

    const float* xp = (MODE == 3) ? g_ctx : x;

    const int lrow = tid >> 1;          // 0..127
    const int lq   = (tid & 1) * 4;     // 0 or 4
    const int tm   = (tid >> 4) * 8;    // 0..120
    const int tn   = (tid & 15) * 8;    // 0..120

    float acc[8][8];
#pragma unroll
    for (int i = 0; i < 8; i++)
#pragma unroll
        for (int j = 0; j < 8; j++) acc[i][j] = 0.0f;

    for (int kt = 0; kt < DMODEL; kt += 8) {
        const float4 av = *(const float4*)(xp + (size_t)(m0 + lrow) * DMODEL + kt + lq);
        const float4 bv = *(const float4*)(W  + (size_t)(n0 + lrow) * DMODEL + kt + lq);
        As[lq + 0][lrow] = av.x; As[lq + 1][lrow] = av.y;
        As[lq + 2][lrow] = av.z; As[lq + 3][lrow] = av.w;
        Bs[lq + 0][lrow] = bv.x; Bs[lq + 1][lrow] = bv.y;
        Bs[lq + 2][lrow] = bv.z; Bs[lq + 3][lrow] = bv.w;
        __syncthreads();

#pragma unroll
        for (int k = 0; k < 8; k++) {
            float a[8], b[8];
            *(float4*)(a)     = *(const float4*)&As[k][tm];
            *(float4*)(a + 4) = *(const float4*)&As[k][tm + 4];
            *(float4*)(b)     = *(const float4*)&Bs[k][tn];
            *(float4*)(b + 4) = *(const float4*)&Bs[k][tn + 4];
#pragma unroll
            for (int i = 0; i < 8; i++)
#pragma unroll
                for (int j = 0; j < 8; j++)
                    acc[i][j] = fmaf(a[i], b[j], acc[i][j]);
        }
        __syncthreads();
    }

    // Epilogue
#pragma unroll
    for (int i = 0; i < 8; i++) {
        const int m = m0 + tm + i;
#pragma unroll
        for (int j = 0; j < 8; j++) {
            const int n = n0 + tn + j;
            const float v = acc[i][j] + bias[n];
            if (MODE <= 2) {
                const int t  = m >> 2;        // m = t*BATCH + b
                const int b  = m & 3;
                const int h  = n >> 6;        // n = h*HDIM + hd
                const int hd = n & 63;
                float* dst = (MODE == 0) ? g_Q : (MODE == 1) ? g_K : g_V;
                dst[((((size_t)b * NHEAD + h) * T_LEN) + t) * HDIM + hd] = v;
            } else {
                const size_t idx = (size_t)m * DMODEL + n;
                out[idx] = v * tdecay[idx];
            }
        }
    }
}

// ---------------------------------------------------------------------------
// Streaming-softmax attention. One thread = one query row.
// Block: 128 threads = 128 query rows; grid (T/128, B*H).
// K/V staged in smem 64-row tiles; online softmax in 8-key chunks so the
// score array lives in 8 registers.
// ---------------------------------------------------------------------------
__global__ void __launch_bounds__(128, 2)
attn_kernel()
{
    __shared__ float Ks[64][64];
    __shared__ float Vs[64][64];

    const int tid  = threadIdx.x;
    const int bh   = blockIdx.y;                       // b*NHEAD + h
    const size_t base = (size_t)bh * T_LEN * HDIM;
    const int qrow = blockIdx.x * 128 + tid;

    const float scale = 0.125f;                        // 1/sqrt(64)

    float q[HDIM], acc[HDIM];
    {
        const float4* qp = (const float4*)(g_Q + base + (size_t)qrow * HDIM);
#pragma unroll
        for (int i = 0; i < 16; i++) {
            const float4 v = qp[i];
            q[4 * i + 0] = v.x * scale;
            q[4 * i + 1] = v.y * scale;
            q[4 * i + 2] = v.z * scale;
            q[4 * i + 3] = v.w * scale;
        }
    }
#pragma unroll
    for (int d = 0; d < HDIM; d++) acc[d] = 0.0f;

    float mrun = -1e30f;
    float lsum = 0.0f;

    for (int kt = 0; kt < T_LEN; kt += 64) {
        // Cooperative tile load: 64x64 floats each for K and V
#pragma unroll
        for (int i = 0; i < 8; i++) {
            const int idx = tid + i * 128;             // 0..1023 float4 slots
            const int r = idx >> 4;
            const int c = (idx & 15) * 4;
            *(float4*)&Ks[r][c] = *(const float4*)(g_K + base + (size_t)(kt + r) * HDIM + c);
            *(float4*)&Vs[r][c] = *(const float4*)(g_V + base + (size_t)(kt + r) * HDIM + c);
        }
        __syncthreads();

        for (int jc = 0; jc < 64; jc += 8) {
            float s[8];
            float mt = -1e30f;
#pragma unroll
            for (int jj = 0; jj < 8; jj++) {
                float sum = 0.0f;
#pragma unroll
                for (int d4 = 0; d4 < 16; d4++) {
                    const float4 kv = *(const float4*)&Ks[jc + jj][d4 * 4];
                    sum = fmaf(q[d4 * 4 + 0], kv.x, sum);
                    sum = fmaf(q[d4 * 4 + 1], kv.y, sum);
                    sum = fmaf(q[d4 * 4 + 2], kv.z, sum);
                    sum = fmaf(q[d4 * 4 + 3], kv.w, sum);
                }
                s[jj] = sum;
                mt = fmaxf(mt, sum);
            }
            const float mnew = fmaxf(mrun, mt);
            const float corr = __expf(mrun - mnew);
            lsum *= corr;
#pragma unroll
            for (int d = 0; d < HDIM; d++) acc[d] *= corr;
#pragma unroll
            for (int jj = 0; jj < 8; jj++) {
                const float p = __expf(s[jj] - mnew);
                lsum += p;
#pragma unroll
                for (int d4 = 0; d4 < 16; d4++) {
                    const float4 vv = *(const float4*)&Vs[jc + jj][d4 * 4];
                    acc[d4 * 4 + 0] = fmaf(p, vv.x, acc[d4 * 4 + 0]);
                    acc[d4 * 4 + 1] = fmaf(p, vv.y, acc[d4 * 4 + 1]);
                    acc[d4 * 4 + 2] = fmaf(p, vv.z, acc[d4 * 4 + 2]);
                    acc[d4 * 4 + 3] = fmaf(p, vv.w, acc[d4 * 4 + 3]);
                }
            }
            mrun = mnew;
        }
        __syncthreads();
    }

    const float inv = 1.0f / lsum;
    const int b = bh >> 4;
    const int h = bh & 15;
    // ctx stored directly in (T, B, D) layout: row = qrow*BATCH + b, col = h*HDIM + hd
    float* op = g_ctx + ((size_t)qrow * BATCH + b) * DMODEL + h * HDIM;
#pragma unroll
    for (int d4 = 0; d4 < 16; d4++) {
        float4 v;
        v.x = acc[d4 * 4 + 0] * inv;
        v.y = acc[d4 * 4 + 1] * inv;
        v.z = acc[d4 * 4 + 2] * inv;
        v.w = acc[d4 * 4 + 3] * inv;
        *(float4*)(op + d4 * 4) = v;
    }
}

// ---------------------------------------------------------------------------
// kernel_launch
// metadata order: query, key, value, time_decay, Wq, bq, Wk, bk, Wv, bv, Wo, bo
// ---------------------------------------------------------------------------
extern "C" void kernel_launch(void* const* d_in, const int* in_sizes, int n_in,
                              void* d_out, int out_size)
{
    const float* query      = (const float*)d_in[0];
    const float* key        = (const float*)d_in[1];
    const float* value      = (const float*)d_in[2];
    const float* time_decay = (const float*)d_in[3];
    const float* Wq = (const float*)d_in[4];
    const float* bq = (const float*)d_in[5];
    const float* Wk = (const float*)d_in[6];
    const float* bk = (const float*)d_in[7];
    const float* Wv = (const float*)d_in[8];
    const float* bv = (const float*)d_in[9];
    const float* Wo = (const float*)d_in[10];
    const float* bo = (const float*)d_in[11];
    float* out = (float*)d_out;

    const dim3 ggrid(DMODEL / 128, MROWS / 128);   // (8, 64)
    gemm_kernel<0><<<ggrid, 256>>>(query, Wq, bq, nullptr, nullptr);
    gemm_kernel<1><<<ggrid, 256>>>(key,   Wk, bk, nullptr, nullptr);
    gemm_kernel<2><<<ggrid, 256>>>(value, Wv, bv, nullptr, nullptr);

    const dim3 agrid(T_LEN / 128, BATCH * NHEAD);  // (16, 64)
    attn_kernel<<<agrid, 128>>>();

    gemm_kernel<3><<<ggrid, 256>>>(nullptr, Wo, bo, out, time_decay);
}

// round 8
// speedup vs baseline: 1.3827x; 1.3827x over previous
#include <cuda_runtime.h>
#include <cuda_bf16.h>
#include <math.h>
#include <stdint.h>

#define T_LEN  2048
#define BATCH  4
#define DMODEL 1024
#define NHEAD  16
#define HDIM   64
#define MROWS  (T_LEN * BATCH)   // 8192

// ---------------------------------------------------------------------------
// Scratch ( __device__ globals: no allocation allowed )
// ---------------------------------------------------------------------------
__device__ float g_Q[(size_t)BATCH * NHEAD * T_LEN * HDIM];
__device__ float g_K[(size_t)BATCH * NHEAD * T_LEN * HDIM];
__device__ float g_V[(size_t)BATCH * NHEAD * T_LEN * HDIM];
__device__ float g_ctx[(size_t)MROWS * DMODEL];

__device__ __nv_bfloat16 g_Ahi[(size_t)MROWS * DMODEL];
__device__ __nv_bfloat16 g_Alo[(size_t)MROWS * DMODEL];
__device__ __nv_bfloat16 g_Whi[(size_t)DMODEL * DMODEL];
__device__ __nv_bfloat16 g_Wlo[(size_t)DMODEL * DMODEL];

// ---------------------------------------------------------------------------
// Portable tensor-core primitives (compute_103-legal: no tcgen05)
// ---------------------------------------------------------------------------
__device__ __forceinline__ uint32_t smem_u32(const void* p) {
    uint32_t a;
    asm("{ .reg .u64 t; cvta.to.shared.u64 t, %1; cvt.u32.u64 %0, t; }"
        : "=r"(a) : "l"(p));
    return a;
}

__device__ __forceinline__ void ldsm_x4(uint32_t& r0, uint32_t& r1,
                                        uint32_t& r2, uint32_t& r3,
                                        uint32_t addr) {
    asm volatile("ldmatrix.sync.aligned.m8n8.x4.shared.b16 {%0,%1,%2,%3}, [%4];"
                 : "=r"(r0), "=r"(r1), "=r"(r2), "=r"(r3) : "r"(addr));
}

__device__ __forceinline__ void mma_bf16(float* d, const uint32_t* a,
                                         uint32_t b0, uint32_t b1) {
    asm volatile(
        "mma.sync.aligned.m16n8k16.row.col.f32.bf16.bf16.f32 "
        "{%0,%1,%2,%3}, {%4,%5,%6,%7}, {%8,%9}, {%0,%1,%2,%3};"
        : "+f"(d[0]), "+f"(d[1]), "+f"(d[2]), "+f"(d[3])
        : "r"(a[0]), "r"(a[1]), "r"(a[2]), "r"(a[3]), "r"(b0), "r"(b1));
}

// ---------------------------------------------------------------------------
// fp32 -> (bf16 hi, bf16 lo) split conversions
// ---------------------------------------------------------------------------
__global__ void __launch_bounds__(256) conv_a(const float* __restrict__ x, int use_ctx) {
    const size_t i = ((size_t)blockIdx.x * 256 + threadIdx.x) * 4;
    const float* src = use_ctx ? g_ctx : x;
    const float4 v = *(const float4*)(src + i);
    __nv_bfloat16 h0 = __float2bfloat16(v.x);
    __nv_bfloat16 h1 = __float2bfloat16(v.y);
    __nv_bfloat16 h2 = __float2bfloat16(v.z);
    __nv_bfloat16 h3 = __float2bfloat16(v.w);
    __nv_bfloat16 l0 = __float2bfloat16(v.x - __bfloat162float(h0));
    __nv_bfloat16 l1 = __float2bfloat16(v.y - __bfloat162float(h1));
    __nv_bfloat16 l2 = __float2bfloat16(v.z - __bfloat162float(h2));
    __nv_bfloat16 l3 = __float2bfloat16(v.w - __bfloat162float(h3));
    *(__nv_bfloat162*)(g_Ahi + i)     = __nv_bfloat162(h0, h1);
    *(__nv_bfloat162*)(g_Ahi + i + 2) = __nv_bfloat162(h2, h3);
    *(__nv_bfloat162*)(g_Alo + i)     = __nv_bfloat162(l0, l1);
    *(__nv_bfloat162*)(g_Alo + i + 2) = __nv_bfloat162(l2, l3);
}

__global__ void __launch_bounds__(256) conv_w(const float* __restrict__ w) {
    const size_t i = ((size_t)blockIdx.x * 256 + threadIdx.x) * 4;
    const float4 v = *(const float4*)(w + i);
    __nv_bfloat16 h0 = __float2bfloat16(v.x);
    __nv_bfloat16 h1 = __float2bfloat16(v.y);
    __nv_bfloat16 h2 = __float2bfloat16(v.z);
    __nv_bfloat16 h3 = __float2bfloat16(v.w);
    __nv_bfloat16 l0 = __float2bfloat16(v.x - __bfloat162float(h0));
    __nv_bfloat16 l1 = __float2bfloat16(v.y - __bfloat162float(h1));
    __nv_bfloat16 l2 = __float2bfloat16(v.z - __bfloat162float(h2));
    __nv_bfloat16 l3 = __float2bfloat16(v.w - __bfloat162float(h3));
    *(__nv_bfloat162*)(g_Whi + i)     = __nv_bfloat162(h0, h1);
    *(__nv_bfloat162*)(g_Whi + i + 2) = __nv_bfloat162(h2, h3);
    *(__nv_bfloat162*)(g_Wlo + i)     = __nv_bfloat162(l0, l1);
    *(__nv_bfloat162*)(g_Wlo + i + 2) = __nv_bfloat162(l2, l3);
}

// ---------------------------------------------------------------------------
// mma.sync bf16x3 GEMM: C[128,128] = A[128,K] @ W[128,K]^T  (+bias, scatter)
//   MODE 0/1/2: scatter into g_Q/g_K/g_V as [B,H,T,HD]
//   MODE 3    : out = (C + bias) * time_decay, row-major [M,D]
// smem: 4 tiles (Ahi,Alo,Whi,Wlo), each 128 rows x 64 bf16 = 16KB,
// 128B rows with XOR-16B swizzle -> conflict-free ldmatrix.
// ---------------------------------------------------------------------------
#define GEMM_SMEM_BYTES 65536

template <int MODE>
__global__ void __launch_bounds__(256)
gemm_mma(const float* __restrict__ bias,
         float* __restrict__ out,
         const float* __restrict__ td)
{
    extern __shared__ __align__(128) char smem[];
    const uint32_t sbase = smem_u32(smem);

    const int tid  = threadIdx.x;
    const int wid  = tid >> 5;
    const int lane = tid & 31;
    const int m0 = blockIdx.y * 128;
    const int n0 = blockIdx.x * 128;

    const int wm = (wid >> 1) * 32;      // warp row base: 0/32/64/96
    const int wn = (wid & 1) * 64;       // warp col base: 0/64

    // ldmatrix lane geometry (A and B tiles share the [row][64k] 128B-row layout)
    const int sub = lane >> 3;           // 0..3
    const int r8  = lane & 7;            // row-in-8
    const uint32_t xr = (uint32_t)r8 << 4;               // swizzle XOR constant
    const int lrow_off = r8 + ((sub & 1) << 3);          // +0 or +8 rows
    const uint32_t lcol_b = (uint32_t)((sub >> 1) << 4); // +0 or +16 bytes

    float acc[2][8][4];
#pragma unroll
    for (int i = 0; i < 2; i++)
#pragma unroll
        for (int j = 0; j < 8; j++)
#pragma unroll
            for (int q = 0; q < 4; q++) acc[i][j][q] = 0.0f;

    for (int kc = 0; kc < 16; ++kc) {
        const int kt = kc * 64;
        // ---- load 4 tiles: Ahi | Alo | Whi | Wlo (each 16KB) ----
#pragma unroll
        for (int t4 = 0; t4 < 4; ++t4) {
            const __nv_bfloat16* src =
                (t4 == 0) ? g_Ahi : (t4 == 1) ? g_Alo : (t4 == 2) ? g_Whi : g_Wlo;
            const int rbase = (t4 < 2) ? m0 : n0;
#pragma unroll
            for (int i = 0; i < 4; ++i) {
                const int s   = tid + i * 256;   // 0..1023 16B slots
                const int row = s >> 3;
                const int chk = s & 7;
                const uint4 v = *(const uint4*)(src + (size_t)(rbase + row) * DMODEL
                                                + kt + chk * 8);
                const uint32_t so = (uint32_t)t4 * 16384u + (uint32_t)row * 128u
                                  + (((uint32_t)chk * 16u) ^ (((uint32_t)row & 7u) << 4));
                *(uint4*)(smem + so) = v;
            }
        }
        __syncthreads();

        // ---- compute: 4 ksteps of 16, 3 split passes ----
#pragma unroll
        for (int ks = 0; ks < 4; ++ks) {
            const uint32_t kb = (uint32_t)ks * 32u + lcol_b;

            uint32_t aHi[2][4], aLo[2][4], bHi[4][4], bLo[4][4];
#pragma unroll
            for (int mi = 0; mi < 2; ++mi) {
                const uint32_t row = (uint32_t)(wm + mi * 16 + lrow_off);
                const uint32_t off = row * 128u + (kb ^ xr);
                ldsm_x4(aHi[mi][0], aHi[mi][1], aHi[mi][2], aHi[mi][3], sbase + off);
                ldsm_x4(aLo[mi][0], aLo[mi][1], aLo[mi][2], aLo[mi][3], sbase + 16384u + off);
            }
#pragma unroll
            for (int nj2 = 0; nj2 < 4; ++nj2) {
                const uint32_t row = (uint32_t)(wn + nj2 * 16 + lrow_off);
                const uint32_t off = row * 128u + (kb ^ xr);
                ldsm_x4(bHi[nj2][0], bHi[nj2][1], bHi[nj2][2], bHi[nj2][3], sbase + 32768u + off);
                ldsm_x4(bLo[nj2][0], bLo[nj2][1], bLo[nj2][2], bLo[nj2][3], sbase + 49152u + off);
            }
#pragma unroll
            for (int mi = 0; mi < 2; ++mi)
#pragma unroll
                for (int nj = 0; nj < 8; ++nj) {
                    const int n2 = nj >> 1;
                    const int hi = nj & 1;
                    mma_bf16(acc[mi][nj], aHi[mi], bHi[n2][hi], bHi[n2][hi + 2]);
                    mma_bf16(acc[mi][nj], aHi[mi], bLo[n2][hi], bLo[n2][hi + 2]);
                    mma_bf16(acc[mi][nj], aLo[mi], bHi[n2][hi], bHi[n2][hi + 2]);
                }
        }
        __syncthreads();
    }

    // ---- epilogue: direct float2 stores (4 lanes/row = one 32B sector) ----
    const int gq = lane >> 2;
    const int tq = lane & 3;
#pragma unroll
    for (int mi = 0; mi < 2; ++mi) {
#pragma unroll
        for (int half = 0; half < 2; ++half) {
            const int m = m0 + wm + mi * 16 + gq + half * 8;
#pragma unroll
            for (int nj = 0; nj < 8; ++nj) {
                const int col = n0 + wn + nj * 8 + tq * 2;
                float v0 = acc[mi][nj][half * 2 + 0] + bias[col];
                float v1 = acc[mi][nj][half * 2 + 1] + bias[col + 1];
                if (MODE <= 2) {
                    const int trow = m >> 2;
                    const int b    = m & 3;
                    const int h    = col >> 6;
                    const int hd   = col & 63;
                    float* dst = (MODE == 0) ? g_Q : (MODE == 1) ? g_K : g_V;
                    float2* p = (float2*)&dst[((((size_t)b * NHEAD + h) * T_LEN) + trow) * HDIM + hd];
                    *p = make_float2(v0, v1);
                } else {
                    const size_t idx = (size_t)m * DMODEL + col;
                    const float2 tv = *(const float2*)&td[idx];
                    *(float2*)&out[idx] = make_float2(v0 * tv.x, v1 * tv.y);
                }
            }
        }
    }
}

// ---------------------------------------------------------------------------
// Streaming-softmax attention (fp32; tensor-core conversion next round)
// ---------------------------------------------------------------------------
__global__ void __launch_bounds__(128, 2)
attn_kernel()
{
    __shared__ float Ks[64][64];
    __shared__ float Vs[64][64];

    const int tid  = threadIdx.x;
    const int bh   = blockIdx.y;
    const size_t base = (size_t)bh * T_LEN * HDIM;
    const int qrow = blockIdx.x * 128 + tid;

    const float scale = 0.125f;

    float q[HDIM], acc[HDIM];
    {
        const float4* qp = (const float4*)(g_Q + base + (size_t)qrow * HDIM);
#pragma unroll
        for (int i = 0; i < 16; i++) {
            const float4 v = qp[i];
            q[4 * i + 0] = v.x * scale;
            q[4 * i + 1] = v.y * scale;
            q[4 * i + 2] = v.z * scale;
            q[4 * i + 3] = v.w * scale;
        }
    }
#pragma unroll
    for (int d = 0; d < HDIM; d++) acc[d] = 0.0f;

    float mrun = -1e30f;
    float lsum = 0.0f;

    for (int kt = 0; kt < T_LEN; kt += 64) {
#pragma unroll
        for (int i = 0; i < 8; i++) {
            const int idx = tid + i * 128;
            const int r = idx >> 4;
            const int c = (idx & 15) * 4;
            *(float4*)&Ks[r][c] = *(const float4*)(g_K + base + (size_t)(kt + r) * HDIM + c);
            *(float4*)&Vs[r][c] = *(const float4*)(g_V + base + (size_t)(kt + r) * HDIM + c);
        }
        __syncthreads();

        for (int jc = 0; jc < 64; jc += 8) {
            float s[8];
            float mt = -1e30f;
#pragma unroll
            for (int jj = 0; jj < 8; jj++) {
                float sum = 0.0f;
#pragma unroll
                for (int d4 = 0; d4 < 16; d4++) {
                    const float4 kv = *(const float4*)&Ks[jc + jj][d4 * 4];
                    sum = fmaf(q[d4 * 4 + 0], kv.x, sum);
                    sum = fmaf(q[d4 * 4 + 1], kv.y, sum);
                    sum = fmaf(q[d4 * 4 + 2], kv.z, sum);
                    sum = fmaf(q[d4 * 4 + 3], kv.w, sum);
                }
                s[jj] = sum;
                mt = fmaxf(mt, sum);
            }
            const float mnew = fmaxf(mrun, mt);
            const float corr = __expf(mrun - mnew);
            lsum *= corr;
#pragma unroll
            for (int d = 0; d < HDIM; d++) acc[d] *= corr;
#pragma unroll
            for (int jj = 0; jj < 8; jj++) {
                const float p = __expf(s[jj] - mnew);
                lsum += p;
#pragma unroll
                for (int d4 = 0; d4 < 16; d4++) {
                    const float4 vv = *(const float4*)&Vs[jc + jj][d4 * 4];
                    acc[d4 * 4 + 0] = fmaf(p, vv.x, acc[d4 * 4 + 0]);
                    acc[d4 * 4 + 1] = fmaf(p, vv.y, acc[d4 * 4 + 1]);
                    acc[d4 * 4 + 2] = fmaf(p, vv.z, acc[d4 * 4 + 2]);
                    acc[d4 * 4 + 3] = fmaf(p, vv.w, acc[d4 * 4 + 3]);
                }
            }
            mrun = mnew;
        }
        __syncthreads();
    }

    const float inv = 1.0f / lsum;
    const int b = bh >> 4;
    const int h = bh & 15;
    float* op = g_ctx + ((size_t)qrow * BATCH + b) * DMODEL + h * HDIM;
#pragma unroll
    for (int d4 = 0; d4 < 16; d4++) {
        float4 v;
        v.x = acc[d4 * 4 + 0] * inv;
        v.y = acc[d4 * 4 + 1] * inv;
        v.z = acc[d4 * 4 + 2] * inv;
        v.w = acc[d4 * 4 + 3] * inv;
        *(float4*)(op + d4 * 4) = v;
    }
}

// ---------------------------------------------------------------------------
// kernel_launch
// order: query, key, value, time_decay, Wq, bq, Wk, bk, Wv, bv, Wo, bo
// ---------------------------------------------------------------------------
extern "C" void kernel_launch(void* const* d_in, const int* in_sizes, int n_in,
                              void* d_out, int out_size)
{
    const float* query      = (const float*)d_in[0];
    const float* key        = (const float*)d_in[1];
    const float* value      = (const float*)d_in[2];
    const float* time_decay = (const float*)d_in[3];
    const float* Wq = (const float*)d_in[4];
    const float* bq = (const float*)d_in[5];
    const float* Wk = (const float*)d_in[6];
    const float* bk = (const float*)d_in[7];
    const float* Wv = (const float*)d_in[8];
    const float* bv = (const float*)d_in[9];
    const float* Wo = (const float*)d_in[10];
    const float* bo = (const float*)d_in[11];
    float* out = (float*)d_out;

    cudaFuncSetAttribute(gemm_mma<0>, cudaFuncAttributeMaxDynamicSharedMemorySize, GEMM_SMEM_BYTES);
    cudaFuncSetAttribute(gemm_mma<1>, cudaFuncAttributeMaxDynamicSharedMemorySize, GEMM_SMEM_BYTES);
    cudaFuncSetAttribute(gemm_mma<2>, cudaFuncAttributeMaxDynamicSharedMemorySize, GEMM_SMEM_BYTES);
    cudaFuncSetAttribute(gemm_mma<3>, cudaFuncAttributeMaxDynamicSharedMemorySize, GEMM_SMEM_BYTES);

    const int convA_blocks = (MROWS * DMODEL) / (256 * 4);   // 8192
    const int convW_blocks = (DMODEL * DMODEL) / (256 * 4);  // 1024
    const dim3 ggrid(DMODEL / 128, MROWS / 128);             // (8, 64)

    conv_a<<<convA_blocks, 256>>>(query, 0);
    conv_w<<<convW_blocks, 256>>>(Wq);
    gemm_mma<0><<<ggrid, 256, GEMM_SMEM_BYTES>>>(bq, nullptr, nullptr);

    conv_a<<<convA_blocks, 256>>>(key, 0);
    conv_w<<<convW_blocks, 256>>>(Wk);
    gemm_mma<1><<<ggrid, 256, GEMM_SMEM_BYTES>>>(bk, nullptr, nullptr);

    conv_a<<<convA_blocks, 256>>>(value, 0);
    conv_w<<<convW_blocks, 256>>>(Wv);
    gemm_mma<2><<<ggrid, 256, GEMM_SMEM_BYTES>>>(bv, nullptr, nullptr);

    const dim3 agrid(T_LEN / 128, BATCH * NHEAD);            // (16, 64)
    attn_kernel<<<agrid, 128>>>();

    conv_a<<<convA_blocks, 256>>>(nullptr, 1);
    conv_w<<<convW_blocks, 256>>>(Wo);
    gemm_mma<3><<<ggrid, 256, GEMM_SMEM_BYTES>>>(bo, out, time_decay);
}

// round 10
// speedup vs baseline: 2.7208x; 1.9677x over previous
#include <cuda_runtime.h>
#include <cuda_bf16.h>
#include <math.h>
#include <stdint.h>

#define T_LEN  2048
#define BATCH  4
#define DMODEL 1024
#define NHEAD  16
#define HDIM   64
#define MROWS  (T_LEN * BATCH)   // 8192
#define NBH    (BATCH * NHEAD)   // 64
#define QKV_ELEMS ((size_t)NBH * T_LEN * HDIM)

// ---------------------------------------------------------------------------
// Scratch ( __device__ globals: no allocation allowed )
// ---------------------------------------------------------------------------
__device__ __nv_bfloat16 g_Qhi[QKV_ELEMS], g_Qlo[QKV_ELEMS];   // [bh][t][hd], prescaled 1/8
__device__ __nv_bfloat16 g_Khi[QKV_ELEMS], g_Klo[QKV_ELEMS];   // [bh][t][hd]
__device__ __nv_bfloat16 g_Vhi[QKV_ELEMS], g_Vlo[QKV_ELEMS];   // [bh][hd][t]  (TRANSPOSED)

__device__ __nv_bfloat16 g_Ahi[(size_t)MROWS * DMODEL];
__device__ __nv_bfloat16 g_Alo[(size_t)MROWS * DMODEL];
__device__ __nv_bfloat16 g_Whi[(size_t)DMODEL * DMODEL];
__device__ __nv_bfloat16 g_Wlo[(size_t)DMODEL * DMODEL];

// ---------------------------------------------------------------------------
// Portable tensor-core primitives (compute_103-legal: no tcgen05)
// ---------------------------------------------------------------------------
__device__ __forceinline__ uint32_t smem_u32(const void* p) {
    uint32_t a;
    asm("{ .reg .u64 t; cvta.to.shared.u64 t, %1; cvt.u32.u64 %0, t; }"
        : "=r"(a) : "l"(p));
    return a;
}

__device__ __forceinline__ void ldsm_x4(uint32_t& r0, uint32_t& r1,
                                        uint32_t& r2, uint32_t& r3,
                                        uint32_t addr) {
    asm volatile("ldmatrix.sync.aligned.m8n8.x4.shared.b16 {%0,%1,%2,%3}, [%4];"
                 : "=r"(r0), "=r"(r1), "=r"(r2), "=r"(r3) : "r"(addr));
}

__device__ __forceinline__ void mma_bf16(float* d, const uint32_t* a,
                                         uint32_t b0, uint32_t b1) {
    asm volatile(
        "mma.sync.aligned.m16n8k16.row.col.f32.bf16.bf16.f32 "
        "{%0,%1,%2,%3}, {%4,%5,%6,%7}, {%8,%9}, {%0,%1,%2,%3};"
        : "+f"(d[0]), "+f"(d[1]), "+f"(d[2]), "+f"(d[3])
        : "r"(a[0]), "r"(a[1]), "r"(a[2]), "r"(a[3]), "r"(b0), "r"(b1));
}

// pack two fp32 -> bf16x2 register (lo element in low half)
__device__ __forceinline__ uint32_t pack_bf(float lo_e, float hi_e) {
    uint32_t r;
    asm("cvt.rn.bf16x2.f32 %0, %1, %2;" : "=r"(r) : "f"(hi_e), "f"(lo_e));
    return r;
}

// ---------------------------------------------------------------------------
// fp32 -> (bf16 hi, bf16 lo) split conversions (GEMM operand prep)
// ---------------------------------------------------------------------------
__global__ void __launch_bounds__(256) conv_a(const float* __restrict__ x) {
    const size_t i = ((size_t)blockIdx.x * 256 + threadIdx.x) * 4;
    const float4 v = *(const float4*)(x + i);
    __nv_bfloat16 h0 = __float2bfloat16(v.x);
    __nv_bfloat16 h1 = __float2bfloat16(v.y);
    __nv_bfloat16 h2 = __float2bfloat16(v.z);
    __nv_bfloat16 h3 = __float2bfloat16(v.w);
    __nv_bfloat16 l0 = __float2bfloat16(v.x - __bfloat162float(h0));
    __nv_bfloat16 l1 = __float2bfloat16(v.y - __bfloat162float(h1));
    __nv_bfloat16 l2 = __float2bfloat16(v.z - __bfloat162float(h2));
    __nv_bfloat16 l3 = __float2bfloat16(v.w - __bfloat162float(h3));
    *(__nv_bfloat162*)(g_Ahi + i)     = __nv_bfloat162(h0, h1);
    *(__nv_bfloat162*)(g_Ahi + i + 2) = __nv_bfloat162(h2, h3);
    *(__nv_bfloat162*)(g_Alo + i)     = __nv_bfloat162(l0, l1);
    *(__nv_bfloat162*)(g_Alo + i + 2) = __nv_bfloat162(l2, l3);
}

__global__ void __launch_bounds__(256) conv_w(const float* __restrict__ w) {
    const size_t i = ((size_t)blockIdx.x * 256 + threadIdx.x) * 4;
    const float4 v = *(const float4*)(w + i);
    __nv_bfloat16 h0 = __float2bfloat16(v.x);
    __nv_bfloat16 h1 = __float2bfloat16(v.y);
    __nv_bfloat16 h2 = __float2bfloat16(v.z);
    __nv_bfloat16 h3 = __float2bfloat16(v.w);
    __nv_bfloat16 l0 = __float2bfloat16(v.x - __bfloat162float(h0));
    __nv_bfloat16 l1 = __float2bfloat16(v.y - __bfloat162float(h1));
    __nv_bfloat16 l2 = __float2bfloat16(v.z - __bfloat162float(h2));
    __nv_bfloat16 l3 = __float2bfloat16(v.w - __bfloat162float(h3));
    *(__nv_bfloat162*)(g_Whi + i)     = __nv_bfloat162(h0, h1);
    *(__nv_bfloat162*)(g_Whi + i + 2) = __nv_bfloat162(h2, h3);
    *(__nv_bfloat162*)(g_Wlo + i)     = __nv_bfloat162(l0, l1);
    *(__nv_bfloat162*)(g_Wlo + i + 2) = __nv_bfloat162(l2, l3);
}

// ---------------------------------------------------------------------------
// mma.sync bf16x3 GEMM: C[128,128] = A[128,K] @ W[128,K]^T  (+bias)
//   MODE 0: Q -> g_Qhi/g_Qlo [bh][t][hd] bf16 hi/lo, scaled by 1/8
//   MODE 1: K -> g_Khi/g_Klo [bh][t][hd]
//   MODE 2: V -> g_Vhi/g_Vlo [bh][hd][t]  (transposed scatter)
//   MODE 3: out = (C + bias) * time_decay, fp32 row-major [M,D]
// ---------------------------------------------------------------------------
#define GEMM_SMEM_BYTES 65536

template <int MODE>
__global__ void __launch_bounds__(256)
gemm_mma(const float* __restrict__ bias,
         float* __restrict__ out,
         const float* __restrict__ td)
{
    extern __shared__ __align__(128) char smem[];
    const uint32_t sbase = smem_u32(smem);

    const int tid  = threadIdx.x;
    const int wid  = tid >> 5;
    const int lane = tid & 31;
    const int m0 = blockIdx.y * 128;
    const int n0 = blockIdx.x * 128;

    const int wm = (wid >> 1) * 32;
    const int wn = (wid & 1) * 64;

    const int sub = lane >> 3;
    const int r8  = lane & 7;
    const uint32_t xr = (uint32_t)r8 << 4;
    const int lrow_off = r8 + ((sub & 1) << 3);
    const uint32_t lcol_b = (uint32_t)((sub >> 1) << 4);

    float acc[2][8][4];
#pragma unroll
    for (int i = 0; i < 2; i++)
#pragma unroll
        for (int j = 0; j < 8; j++)
#pragma unroll
            for (int q = 0; q < 4; q++) acc[i][j][q] = 0.0f;

    for (int kc = 0; kc < 16; ++kc) {
        const int kt = kc * 64;
#pragma unroll
        for (int t4 = 0; t4 < 4; ++t4) {
            const __nv_bfloat16* src =
                (t4 == 0) ? g_Ahi : (t4 == 1) ? g_Alo : (t4 == 2) ? g_Whi : g_Wlo;
            const int rbase = (t4 < 2) ? m0 : n0;
#pragma unroll
            for (int i = 0; i < 4; ++i) {
                const int s   = tid + i * 256;
                const int row = s >> 3;
                const int chk = s & 7;
                const uint4 v = *(const uint4*)(src + (size_t)(rbase + row) * DMODEL
                                                + kt + chk * 8);
                const uint32_t so = (uint32_t)t4 * 16384u + (uint32_t)row * 128u
                                  + (((uint32_t)chk * 16u) ^ (((uint32_t)row & 7u) << 4));
                *(uint4*)(smem + so) = v;
            }
        }
        __syncthreads();

#pragma unroll
        for (int ks = 0; ks < 4; ++ks) {
            const uint32_t kb = (uint32_t)ks * 32u + lcol_b;

            uint32_t aHi[2][4], aLo[2][4], bHi[4][4], bLo[4][4];
#pragma unroll
            for (int mi = 0; mi < 2; ++mi) {
                const uint32_t row = (uint32_t)(wm + mi * 16 + lrow_off);
                const uint32_t off = row * 128u + (kb ^ xr);
                ldsm_x4(aHi[mi][0], aHi[mi][1], aHi[mi][2], aHi[mi][3], sbase + off);
                ldsm_x4(aLo[mi][0], aLo[mi][1], aLo[mi][2], aLo[mi][3], sbase + 16384u + off);
            }
#pragma unroll
            for (int nj2 = 0; nj2 < 4; ++nj2) {
                const uint32_t row = (uint32_t)(wn + nj2 * 16 + lrow_off);
                const uint32_t off = row * 128u + (kb ^ xr);
                ldsm_x4(bHi[nj2][0], bHi[nj2][1], bHi[nj2][2], bHi[nj2][3], sbase + 32768u + off);
                ldsm_x4(bLo[nj2][0], bLo[nj2][1], bLo[nj2][2], bLo[nj2][3], sbase + 49152u + off);
            }
#pragma unroll
            for (int mi = 0; mi < 2; ++mi)
#pragma unroll
                for (int nj = 0; nj < 8; ++nj) {
                    const int n2 = nj >> 1;
                    const int hi = nj & 1;
                    mma_bf16(acc[mi][nj], aHi[mi], bHi[n2][hi], bHi[n2][hi + 2]);
                    mma_bf16(acc[mi][nj], aHi[mi], bLo[n2][hi], bLo[n2][hi + 2]);
                    mma_bf16(acc[mi][nj], aLo[mi], bHi[n2][hi], bHi[n2][hi + 2]);
                }
        }
        __syncthreads();
    }

    // ---- epilogue ----
    const int gq = lane >> 2;
    const int tq = lane & 3;
#pragma unroll
    for (int mi = 0; mi < 2; ++mi) {
#pragma unroll
        for (int half = 0; half < 2; ++half) {
            const int m = m0 + wm + mi * 16 + gq + half * 8;
#pragma unroll
            for (int nj = 0; nj < 8; ++nj) {
                const int col = n0 + wn + nj * 8 + tq * 2;
                float v0 = acc[mi][nj][half * 2 + 0] + bias[col];
                float v1 = acc[mi][nj][half * 2 + 1] + bias[col + 1];
                if (MODE == 3) {
                    const size_t idx = (size_t)m * DMODEL + col;
                    const float2 tv = *(const float2*)&td[idx];
                    *(float2*)&out[idx] = make_float2(v0 * tv.x, v1 * tv.y);
                } else {
                    if (MODE == 0) { v0 *= 0.125f; v1 *= 0.125f; }
                    const int trow = m >> 2;
                    const int b    = m & 3;
                    const int hh   = col >> 6;
                    const int hd   = col & 63;
                    const __nv_bfloat16 h0 = __float2bfloat16(v0);
                    const __nv_bfloat16 h1 = __float2bfloat16(v1);
                    const __nv_bfloat16 l0 = __float2bfloat16(v0 - __bfloat162float(h0));
                    const __nv_bfloat16 l1 = __float2bfloat16(v1 - __bfloat162float(h1));
                    if (MODE == 2) {
                        // transposed: [bh][hd][t]
                        const size_t base = ((size_t)(b * NHEAD + hh) * HDIM + hd) * T_LEN + trow;
                        g_Vhi[base]         = h0;
                        g_Vhi[base + T_LEN] = h1;
                        g_Vlo[base]         = l0;
                        g_Vlo[base + T_LEN] = l1;
                    } else {
                        const size_t base = ((size_t)(b * NHEAD + hh) * T_LEN + trow) * HDIM + hd;
                        __nv_bfloat16* dh = (MODE == 0) ? g_Qhi : g_Khi;
                        __nv_bfloat16* dl = (MODE == 0) ? g_Qlo : g_Klo;
                        *(__nv_bfloat162*)&dh[base] = __nv_bfloat162(h0, h1);
                        *(__nv_bfloat162*)&dl[base] = __nv_bfloat162(l0, l1);
                    }
                }
            }
        }
    }
}

// ---------------------------------------------------------------------------
// Flash attention on mma.sync, bf16x3 for both QK^T and PV.
// CTA: 128 threads (4 warps), 64 q-rows (16/warp), K-tiles of 64 keys.
// smem: Khi@0 Klo@8K Vhi@16K Vlo@24K (Q staged in first 16KB before loop).
// Output written directly as bf16 hi/lo into g_Ahi/g_Alo (O-proj A operand).
// ---------------------------------------------------------------------------
__global__ void __launch_bounds__(128)
attn_mma()
{
    __shared__ __align__(1024) char sm[32768];
    const uint32_t sb = smem_u32(sm);

    const int tid  = threadIdx.x;
    const int wid  = tid >> 5;
    const int lane = tid & 31;
    const int bh   = blockIdx.y;
    const int q0   = blockIdx.x * 64;
    const size_t baseRM = (size_t)bh * T_LEN * HDIM;   // Q,K: [t][hd]
    const size_t baseVT = (size_t)bh * HDIM * T_LEN;   // V:   [hd][t]

    const int sub = lane >> 3;
    const int r8  = lane & 7;
    const uint32_t xr = (uint32_t)r8 << 4;
    const int lrow = r8 + ((sub & 1) << 3);
    const uint32_t lcol = (uint32_t)((sub >> 1) << 4);

    // ---- stage Q (hi @0, lo @8192), pull fragments to registers ----
#pragma unroll
    for (int i = 0; i < 4; ++i) {
        const int s = tid + i * 128;
        const int row = s >> 3, c16 = s & 7;
        const uint32_t so = (uint32_t)row * 128u
            + (((uint32_t)c16 * 16u) ^ (((uint32_t)row & 7u) << 4));
        const size_t g = baseRM + (size_t)(q0 + row) * HDIM + c16 * 8;
        *(uint4*)(sm + so)        = *(const uint4*)(g_Qhi + g);
        *(uint4*)(sm + 8192 + so) = *(const uint4*)(g_Qlo + g);
    }
    __syncthreads();

    uint32_t qhi[4][4], qlo[4][4];
    {
        const uint32_t qrow = (uint32_t)(wid * 16 + lrow);
#pragma unroll
        for (int ks = 0; ks < 4; ++ks) {
            const uint32_t off = qrow * 128u + (((uint32_t)ks * 32u + lcol) ^ xr);
            ldsm_x4(qhi[ks][0], qhi[ks][1], qhi[ks][2], qhi[ks][3], sb + off);
            ldsm_x4(qlo[ks][0], qlo[ks][1], qlo[ks][2], qlo[ks][3], sb + 8192 + off);
        }
    }
    __syncthreads();

    float ctx[8][4];
#pragma unroll
    for (int j = 0; j < 8; ++j)
#pragma unroll
        for (int q = 0; q < 4; ++q) ctx[j][q] = 0.0f;
    float mr0 = -1e30f, mr1 = -1e30f, lr0 = 0.0f, lr1 = 0.0f;

    for (int kt = 0; kt < T_LEN; kt += 64) {
        // ---- load K / V tiles (bf16 hi/lo, swizzled) ----
#pragma unroll
        for (int i = 0; i < 4; ++i) {
            const int s = tid + i * 128;
            const int row = s >> 3, c16 = s & 7;
            const uint32_t so = (uint32_t)row * 128u
                + (((uint32_t)c16 * 16u) ^ (((uint32_t)row & 7u) << 4));
            const size_t gk = baseRM + (size_t)(kt + row) * HDIM + c16 * 8;
            const size_t gv = baseVT + (size_t)row * T_LEN + kt + c16 * 8;
            *(uint4*)(sm + so)         = *(const uint4*)(g_Khi + gk);
            *(uint4*)(sm + 8192 + so)  = *(const uint4*)(g_Klo + gk);
            *(uint4*)(sm + 16384 + so) = *(const uint4*)(g_Vhi + gv);
            *(uint4*)(sm + 24576 + so) = *(const uint4*)(g_Vlo + gv);
        }
        __syncthreads();

        // ---- S = (Q/8) K^T, bf16x3 ----
        float sacc[8][4];
#pragma unroll
        for (int j = 0; j < 8; ++j)
#pragma unroll
            for (int q = 0; q < 4; ++q) sacc[j][q] = 0.0f;

#pragma unroll
        for (int ks = 0; ks < 4; ++ks) {
            uint32_t kh[4][4], kl[4][4];
#pragma unroll
            for (int n2 = 0; n2 < 4; ++n2) {
                const uint32_t off = (uint32_t)(n2 * 16 + lrow) * 128u
                                   + (((uint32_t)ks * 32u + lcol) ^ xr);
                ldsm_x4(kh[n2][0], kh[n2][1], kh[n2][2], kh[n2][3], sb + off);
                ldsm_x4(kl[n2][0], kl[n2][1], kl[n2][2], kl[n2][3], sb + 8192 + off);
            }
#pragma unroll
            for (int nj = 0; nj < 8; ++nj) {
                const int n2 = nj >> 1, h = nj & 1;
                mma_bf16(sacc[nj], qhi[ks], kh[n2][h], kh[n2][h + 2]);
                mma_bf16(sacc[nj], qhi[ks], kl[n2][h], kl[n2][h + 2]);
                mma_bf16(sacc[nj], qlo[ks], kh[n2][h], kh[n2][h + 2]);
            }
        }

        // ---- online softmax stats (rows gq, gq+8 per lane) ----
        float mt0 = -1e30f, mt1 = -1e30f;
#pragma unroll
        for (int nj = 0; nj < 8; ++nj) {
            mt0 = fmaxf(mt0, fmaxf(sacc[nj][0], sacc[nj][1]));
            mt1 = fmaxf(mt1, fmaxf(sacc[nj][2], sacc[nj][3]));
        }
        mt0 = fmaxf(mt0, __shfl_xor_sync(0xffffffffu, mt0, 1));
        mt0 = fmaxf(mt0, __shfl_xor_sync(0xffffffffu, mt0, 2));
        mt1 = fmaxf(mt1, __shfl_xor_sync(0xffffffffu, mt1, 1));
        mt1 = fmaxf(mt1, __shfl_xor_sync(0xffffffffu, mt1, 2));
        const float mn0 = fmaxf(mr0, mt0);
        const float mn1 = fmaxf(mr1, mt1);
        const float cc0 = __expf(mr0 - mn0);
        const float cc1 = __expf(mr1 - mn1);
        mr0 = mn0; mr1 = mn1;
#pragma unroll
        for (int nj = 0; nj < 8; ++nj) {
            ctx[nj][0] *= cc0; ctx[nj][1] *= cc0;
            ctx[nj][2] *= cc1; ctx[nj][3] *= cc1;
        }

        // ---- P = exp(S - m), split hi/lo, and P·V per 16-key k-step ----
        float s0 = 0.0f, s1 = 0.0f;
#pragma unroll
        for (int kk = 0; kk < 4; ++kk) {
            uint32_t ahi[4], alo[4];
#pragma unroll
            for (int t2 = 0; t2 < 2; ++t2) {
                const int nj = 2 * kk + t2;
                const float p0 = __expf(sacc[nj][0] - mn0);
                const float p1 = __expf(sacc[nj][1] - mn0);
                const float p2 = __expf(sacc[nj][2] - mn1);
                const float p3 = __expf(sacc[nj][3] - mn1);
                s0 += p0 + p1; s1 += p2 + p3;
                const __nv_bfloat16 b0 = __float2bfloat16(p0);
                const __nv_bfloat16 b1 = __float2bfloat16(p1);
                const __nv_bfloat16 b2 = __float2bfloat16(p2);
                const __nv_bfloat16 b3 = __float2bfloat16(p3);
                ahi[2 * t2 + 0] = pack_bf(__bfloat162float(b0), __bfloat162float(b1));
                ahi[2 * t2 + 1] = pack_bf(__bfloat162float(b2), __bfloat162float(b3));
                alo[2 * t2 + 0] = pack_bf(p0 - __bfloat162float(b0), p1 - __bfloat162float(b1));
                alo[2 * t2 + 1] = pack_bf(p2 - __bfloat162float(b2), p3 - __bfloat162float(b3));
            }
            uint32_t vh[4][4], vl[4][4];
#pragma unroll
            for (int n2 = 0; n2 < 4; ++n2) {
                const uint32_t off = (uint32_t)(n2 * 16 + lrow) * 128u
                                   + (((uint32_t)kk * 32u + lcol) ^ xr);
                ldsm_x4(vh[n2][0], vh[n2][1], vh[n2][2], vh[n2][3], sb + 16384 + off);
                ldsm_x4(vl[n2][0], vl[n2][1], vl[n2][2], vl[n2][3], sb + 24576 + off);
            }
#pragma unroll
            for (int nj = 0; nj < 8; ++nj) {
                const int n2 = nj >> 1, h = nj & 1;
                mma_bf16(ctx[nj], ahi, vh[n2][h], vh[n2][h + 2]);
                mma_bf16(ctx[nj], ahi, vl[n2][h], vl[n2][h + 2]);
                mma_bf16(ctx[nj], alo, vh[n2][h], vh[n2][h + 2]);
            }
        }
        s0 += __shfl_xor_sync(0xffffffffu, s0, 1);
        s0 += __shfl_xor_sync(0xffffffffu, s0, 2);
        s1 += __shfl_xor_sync(0xffffffffu, s1, 1);
        s1 += __shfl_xor_sync(0xffffffffu, s1, 2);
        lr0 = lr0 * cc0 + s0;
        lr1 = lr1 * cc1 + s1;

        __syncthreads();
    }

    // ---- epilogue: normalize, write ctx as bf16 hi/lo straight into O-proj A ----
    const float i0 = 1.0f / lr0;
    const float i1 = 1.0f / lr1;
    const int b  = bh >> 4;
    const int hh = bh & 15;
    const int gq = lane >> 2;
    const int tq = lane & 3;
    const int r0 = q0 + wid * 16 + gq;
    const int r1 = r0 + 8;
#pragma unroll
    for (int nj = 0; nj < 8; ++nj) {
        const int col = hh * 64 + nj * 8 + tq * 2;
        {
            const float v0 = ctx[nj][0] * i0;
            const float v1 = ctx[nj][1] * i0;
            const __nv_bfloat16 h0 = __float2bfloat16(v0);
            const __nv_bfloat16 h1 = __float2bfloat16(v1);
            const size_t idx = ((size_t)r0 * BATCH + b) * DMODEL + col;
            *(__nv_bfloat162*)&g_Ahi[idx] = __nv_bfloat162(h0, h1);
            *(__nv_bfloat162*)&g_Alo[idx] =
                __nv_bfloat162(__float2bfloat16(v0 - __bfloat162float(h0)),
                               __float2bfloat16(v1 - __bfloat162float(h1)));
        }
        {
            const float v0 = ctx[nj][2] * i1;
            const float v1 = ctx[nj][3] * i1;
            const __nv_bfloat16 h0 = __float2bfloat16(v0);
            const __nv_bfloat16 h1 = __float2bfloat16(v1);
            const size_t idx = ((size_t)r1 * BATCH + b) * DMODEL + col;
            *(__nv_bfloat162*)&g_Ahi[idx] = __nv_bfloat162(h0, h1);
            *(__nv_bfloat162*)&g_Alo[idx] =
                __nv_bfloat162(__float2bfloat16(v0 - __bfloat162float(h0)),
                               __float2bfloat16(v1 - __bfloat162float(h1)));
        }
    }
}

// ---------------------------------------------------------------------------
// kernel_launch
// order: query, key, value, time_decay, Wq, bq, Wk, bk, Wv, bv, Wo, bo
// ---------------------------------------------------------------------------
extern "C" void kernel_launch(void* const* d_in, const int* in_sizes, int n_in,
                              void* d_out, int out_size)
{
    const float* query      = (const float*)d_in[0];
    const float* key        = (const float*)d_in[1];
    const float* value      = (const float*)d_in[2];
    const float* time_decay = (const float*)d_in[3];
    const float* Wq = (const float*)d_in[4];
    const float* bq = (const float*)d_in[5];
    const float* Wk = (const float*)d_in[6];
    const float* bk = (const float*)d_in[7];
    const float* Wv = (const float*)d_in[8];
    const float* bv = (const float*)d_in[9];
    const float* Wo = (const float*)d_in[10];
    const float* bo = (const float*)d_in[11];
    float* out = (float*)d_out;

    cudaFuncSetAttribute(gemm_mma<0>, cudaFuncAttributeMaxDynamicSharedMemorySize, GEMM_SMEM_BYTES);
    cudaFuncSetAttribute(gemm_mma<1>, cudaFuncAttributeMaxDynamicSharedMemorySize, GEMM_SMEM_BYTES);
    cudaFuncSetAttribute(gemm_mma<2>, cudaFuncAttributeMaxDynamicSharedMemorySize, GEMM_SMEM_BYTES);
    cudaFuncSetAttribute(gemm_mma<3>, cudaFuncAttributeMaxDynamicSharedMemorySize, GEMM_SMEM_BYTES);

    const int convA_blocks = (MROWS * DMODEL) / (256 * 4);   // 8192
    const int convW_blocks = (DMODEL * DMODEL) / (256 * 4);  // 1024
    const dim3 ggrid(DMODEL / 128, MROWS / 128);             // (8, 64)

    conv_a<<<convA_blocks, 256>>>(query);
    conv_w<<<convW_blocks, 256>>>(Wq);
    gemm_mma<0><<<ggrid, 256, GEMM_SMEM_BYTES>>>(bq, nullptr, nullptr);

    conv_a<<<convA_blocks, 256>>>(key);
    conv_w<<<convW_blocks, 256>>>(Wk);
    gemm_mma<1><<<ggrid, 256, GEMM_SMEM_BYTES>>>(bk, nullptr, nullptr);

    conv_a<<<convA_blocks, 256>>>(value);
    conv_w<<<convW_blocks, 256>>>(Wv);
    gemm_mma<2><<<ggrid, 256, GEMM_SMEM_BYTES>>>(bv, nullptr, nullptr);

    const dim3 agrid(T_LEN / 64, NBH);                       // (32, 64)
    attn_mma<<<agrid, 128>>>();

    conv_w<<<convW_blocks, 256>>>(Wo);
    gemm_mma<3><<<ggrid, 256, GEMM_SMEM_BYTES>>>(bo, out, time_decay);
}

// round 11
// speedup vs baseline: 3.2446x; 1.1925x over previous
#include <cuda_runtime.h>
#include <cuda_bf16.h>
#include <math.h>
#include <stdint.h>

#define T_LEN  2048
#define BATCH  4
#define DMODEL 1024
#define NHEAD  16
#define HDIM   64
#define MROWS  (T_LEN * BATCH)   // 8192
#define NBH    (BATCH * NHEAD)   // 64
#define QKV_ELEMS ((size_t)NBH * T_LEN * HDIM)

// ---------------------------------------------------------------------------
// Scratch ( __device__ globals: no allocation allowed )
// ---------------------------------------------------------------------------
__device__ __nv_bfloat16 g_Qhi[QKV_ELEMS], g_Qlo[QKV_ELEMS];   // [bh][t][hd], prescaled 1/8
__device__ __nv_bfloat16 g_Khi[QKV_ELEMS], g_Klo[QKV_ELEMS];   // [bh][t][hd]
__device__ __nv_bfloat16 g_Vhi[QKV_ELEMS], g_Vlo[QKV_ELEMS];   // [bh][hd][t]  (TRANSPOSED)

// slotted: A slots 0..2 = q/k/v inputs (slot 0 reused by attn output for O-proj)
__device__ __nv_bfloat16 g_Ahi[(size_t)3 * MROWS * DMODEL];
__device__ __nv_bfloat16 g_Alo[(size_t)3 * MROWS * DMODEL];
// W slots 0..3 = Wq, Wk, Wv, Wo
__device__ __nv_bfloat16 g_Whi[(size_t)4 * DMODEL * DMODEL];
__device__ __nv_bfloat16 g_Wlo[(size_t)4 * DMODEL * DMODEL];

// ---------------------------------------------------------------------------
// Primitives (compute_103-legal: mma.sync / ldmatrix / cp.async only)
// ---------------------------------------------------------------------------
__device__ __forceinline__ uint32_t smem_u32(const void* p) {
    uint32_t a;
    asm("{ .reg .u64 t; cvta.to.shared.u64 t, %1; cvt.u32.u64 %0, t; }"
        : "=r"(a) : "l"(p));
    return a;
}

__device__ __forceinline__ void ldsm_x4(uint32_t& r0, uint32_t& r1,
                                        uint32_t& r2, uint32_t& r3,
                                        uint32_t addr) {
    asm volatile("ldmatrix.sync.aligned.m8n8.x4.shared.b16 {%0,%1,%2,%3}, [%4];"
                 : "=r"(r0), "=r"(r1), "=r"(r2), "=r"(r3) : "r"(addr));
}

__device__ __forceinline__ void mma_bf16(float* d, const uint32_t* a,
                                         uint32_t b0, uint32_t b1) {
    asm volatile(
        "mma.sync.aligned.m16n8k16.row.col.f32.bf16.bf16.f32 "
        "{%0,%1,%2,%3}, {%4,%5,%6,%7}, {%8,%9}, {%0,%1,%2,%3};"
        : "+f"(d[0]), "+f"(d[1]), "+f"(d[2]), "+f"(d[3])
        : "r"(a[0]), "r"(a[1]), "r"(a[2]), "r"(a[3]), "r"(b0), "r"(b1));
}

__device__ __forceinline__ uint32_t pack_bf(float lo_e, float hi_e) {
    uint32_t r;
    asm("cvt.rn.bf16x2.f32 %0, %1, %2;" : "=r"(r) : "f"(hi_e), "f"(lo_e));
    return r;
}

__device__ __forceinline__ void cp16(uint32_t dst, const void* src) {
    asm volatile("cp.async.cg.shared.global [%0], [%1], 16;"
                 :: "r"(dst), "l"((uint64_t)__cvta_generic_to_global(src)));
}
#define CP_COMMIT() asm volatile("cp.async.commit_group;")
#define CP_WAIT(n)  asm volatile("cp.async.wait_group %0;" :: "n"(n))

// ---------------------------------------------------------------------------
// fp32 -> (bf16 hi, bf16 lo) split conversions, merged launches
// ---------------------------------------------------------------------------
__global__ void __launch_bounds__(256)
conv_a_all(const float* __restrict__ q, const float* __restrict__ k,
           const float* __restrict__ v)
{
    const int slot = blockIdx.y;
    const float* src = (slot == 0) ? q : (slot == 1) ? k : v;
    const size_t i = ((size_t)blockIdx.x * 256 + threadIdx.x) * 4;
    const size_t o = (size_t)slot * MROWS * DMODEL + i;
    const float4 x = *(const float4*)(src + i);
    __nv_bfloat16 h0 = __float2bfloat16(x.x);
    __nv_bfloat16 h1 = __float2bfloat16(x.y);
    __nv_bfloat16 h2 = __float2bfloat16(x.z);
    __nv_bfloat16 h3 = __float2bfloat16(x.w);
    *(__nv_bfloat162*)(g_Ahi + o)     = __nv_bfloat162(h0, h1);
    *(__nv_bfloat162*)(g_Ahi + o + 2) = __nv_bfloat162(h2, h3);
    *(__nv_bfloat162*)(g_Alo + o) =
        __nv_bfloat162(__float2bfloat16(x.x - __bfloat162float(h0)),
                       __float2bfloat16(x.y - __bfloat162float(h1)));
    *(__nv_bfloat162*)(g_Alo + o + 2) =
        __nv_bfloat162(__float2bfloat16(x.z - __bfloat162float(h2)),
                       __float2bfloat16(x.w - __bfloat162float(h3)));
}

__global__ void __launch_bounds__(256)
conv_w_all(const float* __restrict__ wq, const float* __restrict__ wk,
           const float* __restrict__ wv, const float* __restrict__ wo)
{
    const int slot = blockIdx.y;
    const float* src = (slot == 0) ? wq : (slot == 1) ? wk : (slot == 2) ? wv : wo;
    const size_t i = ((size_t)blockIdx.x * 256 + threadIdx.x) * 4;
    const size_t o = (size_t)slot * DMODEL * DMODEL + i;
    const float4 x = *(const float4*)(src + i);
    __nv_bfloat16 h0 = __float2bfloat16(x.x);
    __nv_bfloat16 h1 = __float2bfloat16(x.y);
    __nv_bfloat16 h2 = __float2bfloat16(x.z);
    __nv_bfloat16 h3 = __float2bfloat16(x.w);
    *(__nv_bfloat162*)(g_Whi + o)     = __nv_bfloat162(h0, h1);
    *(__nv_bfloat162*)(g_Whi + o + 2) = __nv_bfloat162(h2, h3);
    *(__nv_bfloat162*)(g_Wlo + o) =
        __nv_bfloat162(__float2bfloat16(x.x - __bfloat162float(h0)),
                       __float2bfloat16(x.y - __bfloat162float(h1)));
    *(__nv_bfloat162*)(g_Wlo + o + 2) =
        __nv_bfloat162(__float2bfloat16(x.z - __bfloat162float(h2)),
                       __float2bfloat16(x.w - __bfloat162float(h3)));
}

// ---------------------------------------------------------------------------
// bf16x3 GEMM with cp.async 2-stage pipeline.
//   mode 0: Q -> g_Qhi/lo [bh][t][hd], scaled 1/8
//   mode 1: K -> g_Khi/lo [bh][t][hd]
//   mode 2: V -> g_Vhi/lo [bh][hd][t] (transposed scatter)
//   mode 3: out = (C + bias) * time_decay (A = slot 0, W = slot 3)
// smem: 2 stages x {Ahi,Alo,Whi,Wlo tiles of 16KB} = 131072 B.
// ---------------------------------------------------------------------------
#define GEMM_SMEM_BYTES 131072

__device__ __forceinline__ void gemm_load_chunk(
    uint32_t sbase, uint32_t stage, int tid, int m0, int n0, int kt,
    const __nv_bfloat16* aHi, const __nv_bfloat16* aLo,
    const __nv_bfloat16* wHi, const __nv_bfloat16* wLo)
{
#pragma unroll
    for (int t4 = 0; t4 < 4; ++t4) {
        const __nv_bfloat16* src = (t4 == 0) ? aHi : (t4 == 1) ? aLo
                                 : (t4 == 2) ? wHi : wLo;
        const int rbase = (t4 < 2) ? m0 : n0;
#pragma unroll
        for (int i = 0; i < 4; ++i) {
            const int s   = tid + i * 256;
            const int row = s >> 3;
            const int chk = s & 7;
            const uint32_t so = stage + (uint32_t)t4 * 16384u + (uint32_t)row * 128u
                              + (((uint32_t)chk * 16u) ^ (((uint32_t)row & 7u) << 4));
            cp16(sbase + so, src + (size_t)(rbase + row) * DMODEL + kt + chk * 8);
        }
    }
}

__global__ void __launch_bounds__(256)
gemm_all(const float* __restrict__ b0, const float* __restrict__ b1,
         const float* __restrict__ b2, float* __restrict__ out,
         const float* __restrict__ td, int which)
{
    extern __shared__ __align__(128) char smem[];
    const uint32_t sbase = smem_u32(smem);

    const int mode = (which < 0) ? (int)blockIdx.z : which;
    const float* bias = (mode == 1) ? b1 : (mode == 2) ? b2 : b0;

    const size_t aoff = (mode < 3) ? (size_t)mode * MROWS * DMODEL : 0;
    const size_t woff = (size_t)mode * DMODEL * DMODEL;
    const __nv_bfloat16* aHi = g_Ahi + aoff;
    const __nv_bfloat16* aLo = g_Alo + aoff;
    const __nv_bfloat16* wHi = g_Whi + woff;
    const __nv_bfloat16* wLo = g_Wlo + woff;

    const int tid  = threadIdx.x;
    const int wid  = tid >> 5;
    const int lane = tid & 31;
    const int m0 = blockIdx.y * 128;
    const int n0 = blockIdx.x * 128;

    const int wm = (wid >> 1) * 32;
    const int wn = (wid & 1) * 64;

    const int sub = lane >> 3;
    const int r8  = lane & 7;
    const uint32_t xr = (uint32_t)r8 << 4;
    const int lrow_off = r8 + ((sub & 1) << 3);
    const uint32_t lcol_b = (uint32_t)((sub >> 1) << 4);

    float acc[2][8][4];
#pragma unroll
    for (int i = 0; i < 2; i++)
#pragma unroll
        for (int j = 0; j < 8; j++)
#pragma unroll
            for (int q = 0; q < 4; q++) acc[i][j][q] = 0.0f;

    gemm_load_chunk(sbase, 0, tid, m0, n0, 0, aHi, aLo, wHi, wLo);
    CP_COMMIT();

    for (int kc = 0; kc < 16; ++kc) {
        if (kc < 15) {
            gemm_load_chunk(sbase, (uint32_t)((kc + 1) & 1) * 65536u, tid,
                            m0, n0, (kc + 1) * 64, aHi, aLo, wHi, wLo);
            CP_COMMIT();
            CP_WAIT(1);
        } else {
            CP_WAIT(0);
        }
        __syncthreads();

        const uint32_t st = sbase + (uint32_t)(kc & 1) * 65536u;
#pragma unroll
        for (int ks = 0; ks < 4; ++ks) {
            const uint32_t kb = (uint32_t)ks * 32u + lcol_b;

            uint32_t aHiF[2][4], aLoF[2][4], bHiF[4][4], bLoF[4][4];
#pragma unroll
            for (int mi = 0; mi < 2; ++mi) {
                const uint32_t row = (uint32_t)(wm + mi * 16 + lrow_off);
                const uint32_t off = row * 128u + (kb ^ xr);
                ldsm_x4(aHiF[mi][0], aHiF[mi][1], aHiF[mi][2], aHiF[mi][3], st + off);
                ldsm_x4(aLoF[mi][0], aLoF[mi][1], aLoF[mi][2], aLoF[mi][3], st + 16384u + off);
            }
#pragma unroll
            for (int nj2 = 0; nj2 < 4; ++nj2) {
                const uint32_t row = (uint32_t)(wn + nj2 * 16 + lrow_off);
                const uint32_t off = row * 128u + (kb ^ xr);
                ldsm_x4(bHiF[nj2][0], bHiF[nj2][1], bHiF[nj2][2], bHiF[nj2][3], st + 32768u + off);
                ldsm_x4(bLoF[nj2][0], bLoF[nj2][1], bLoF[nj2][2], bLoF[nj2][3], st + 49152u + off);
            }
#pragma unroll
            for (int mi = 0; mi < 2; ++mi)
#pragma unroll
                for (int nj = 0; nj < 8; ++nj) {
                    const int n2 = nj >> 1;
                    const int hi = nj & 1;
                    mma_bf16(acc[mi][nj], aHiF[mi], bHiF[n2][hi], bHiF[n2][hi + 2]);
                    mma_bf16(acc[mi][nj], aHiF[mi], bLoF[n2][hi], bLoF[n2][hi + 2]);
                    mma_bf16(acc[mi][nj], aLoF[mi], bHiF[n2][hi], bHiF[n2][hi + 2]);
                }
        }
        __syncthreads();
    }

    // ---- epilogue ----
    const int gq = lane >> 2;
    const int tq = lane & 3;
#pragma unroll
    for (int mi = 0; mi < 2; ++mi) {
#pragma unroll
        for (int half = 0; half < 2; ++half) {
            const int m = m0 + wm + mi * 16 + gq + half * 8;
#pragma unroll
            for (int nj = 0; nj < 8; ++nj) {
                const int col = n0 + wn + nj * 8 + tq * 2;
                float v0 = acc[mi][nj][half * 2 + 0] + bias[col];
                float v1 = acc[mi][nj][half * 2 + 1] + bias[col + 1];
                if (mode == 3) {
                    const size_t idx = (size_t)m * DMODEL + col;
                    const float2 tv = *(const float2*)&td[idx];
                    *(float2*)&out[idx] = make_float2(v0 * tv.x, v1 * tv.y);
                } else {
                    if (mode == 0) { v0 *= 0.125f; v1 *= 0.125f; }
                    const int trow = m >> 2;
                    const int b    = m & 3;
                    const int hh   = col >> 6;
                    const int hd   = col & 63;
                    const __nv_bfloat16 h0 = __float2bfloat16(v0);
                    const __nv_bfloat16 h1 = __float2bfloat16(v1);
                    const __nv_bfloat16 l0 = __float2bfloat16(v0 - __bfloat162float(h0));
                    const __nv_bfloat16 l1 = __float2bfloat16(v1 - __bfloat162float(h1));
                    if (mode == 2) {
                        const size_t base = ((size_t)(b * NHEAD + hh) * HDIM + hd) * T_LEN + trow;
                        g_Vhi[base]         = h0;
                        g_Vhi[base + T_LEN] = h1;
                        g_Vlo[base]         = l0;
                        g_Vlo[base + T_LEN] = l1;
                    } else {
                        const size_t base = ((size_t)(b * NHEAD + hh) * T_LEN + trow) * HDIM + hd;
                        __nv_bfloat16* dh = (mode == 0) ? g_Qhi : g_Khi;
                        __nv_bfloat16* dl = (mode == 0) ? g_Qlo : g_Klo;
                        *(__nv_bfloat162*)&dh[base] = __nv_bfloat162(h0, h1);
                        *(__nv_bfloat162*)&dl[base] = __nv_bfloat162(l0, l1);
                    }
                }
            }
        }
    }
}

// ---------------------------------------------------------------------------
// Flash attention on mma.sync, bf16x3, cp.async 2-stage K/V pipeline.
// CTA: 128 threads (4 warps), 64 q-rows. smem: 2 stages x 32KB
// {Khi,Klo,Vhi,Vlo @ +0/+8K/+16K/+24K}; Q staged through stage 1.
// Output -> bf16 hi/lo into g_Ahi/g_Alo slot 0 (O-proj A operand).
// ---------------------------------------------------------------------------
#define ATTN_SMEM_BYTES 65536

__device__ __forceinline__ void attn_load_chunk(
    uint32_t sbase, uint32_t stage, int tid, int kt,
    size_t baseRM, size_t baseVT)
{
#pragma unroll
    for (int i = 0; i < 4; ++i) {
        const int s = tid + i * 128;
        const int row = s >> 3, c16 = s & 7;
        const uint32_t so = stage + (uint32_t)row * 128u
            + (((uint32_t)c16 * 16u) ^ (((uint32_t)row & 7u) << 4));
        const size_t gk = baseRM + (size_t)(kt + row) * HDIM + c16 * 8;
        const size_t gv = baseVT + (size_t)row * T_LEN + kt + c16 * 8;
        cp16(sbase + so,          g_Khi + gk);
        cp16(sbase + 8192u + so,  g_Klo + gk);
        cp16(sbase + 16384u + so, g_Vhi + gv);
        cp16(sbase + 24576u + so, g_Vlo + gv);
    }
}

__global__ void __launch_bounds__(128)
attn_mma()
{
    extern __shared__ __align__(1024) char sm[];
    const uint32_t sb = smem_u32(sm);

    const int tid  = threadIdx.x;
    const int wid  = tid >> 5;
    const int lane = tid & 31;
    const int bh   = blockIdx.y;
    const int q0   = blockIdx.x * 64;
    const size_t baseRM = (size_t)bh * T_LEN * HDIM;
    const size_t baseVT = (size_t)bh * HDIM * T_LEN;

    const int sub = lane >> 3;
    const int r8  = lane & 7;
    const uint32_t xr = (uint32_t)r8 << 4;
    const int lrow = r8 + ((sub & 1) << 3);
    const uint32_t lcol = (uint32_t)((sub >> 1) << 4);

    // ---- prologue: chunk0 -> stage0; Q -> stage1 area ----
    attn_load_chunk(sb, 0, tid, 0, baseRM, baseVT);
    CP_COMMIT();
#pragma unroll
    for (int i = 0; i < 4; ++i) {
        const int s = tid + i * 128;
        const int row = s >> 3, c16 = s & 7;
        const uint32_t so = (uint32_t)row * 128u
            + (((uint32_t)c16 * 16u) ^ (((uint32_t)row & 7u) << 4));
        const size_t g = baseRM + (size_t)(q0 + row) * HDIM + c16 * 8;
        cp16(sb + 32768u + so, g_Qhi + g);
        cp16(sb + 40960u + so, g_Qlo + g);
    }
    CP_COMMIT();
    CP_WAIT(0);
    __syncthreads();

    uint32_t qhi[4][4], qlo[4][4];
    {
        const uint32_t qrow = (uint32_t)(wid * 16 + lrow);
#pragma unroll
        for (int ks = 0; ks < 4; ++ks) {
            const uint32_t off = qrow * 128u + (((uint32_t)ks * 32u + lcol) ^ xr);
            ldsm_x4(qhi[ks][0], qhi[ks][1], qhi[ks][2], qhi[ks][3], sb + 32768u + off);
            ldsm_x4(qlo[ks][0], qlo[ks][1], qlo[ks][2], qlo[ks][3], sb + 40960u + off);
        }
    }
    __syncthreads();   // stage1 free for chunk1

    float ctx[8][4];
#pragma unroll
    for (int j = 0; j < 8; ++j)
#pragma unroll
        for (int q = 0; q < 4; ++q) ctx[j][q] = 0.0f;
    float mr0 = -1e30f, mr1 = -1e30f, lr0 = 0.0f, lr1 = 0.0f;

    for (int c = 0; c < T_LEN / 64; ++c) {
        if (c < T_LEN / 64 - 1) {
            attn_load_chunk(sb, (uint32_t)((c + 1) & 1) * 32768u, tid,
                            (c + 1) * 64, baseRM, baseVT);
            CP_COMMIT();
            CP_WAIT(1);
        } else {
            CP_WAIT(0);
        }
        __syncthreads();

        const uint32_t st = sb + (uint32_t)(c & 1) * 32768u;

        // ---- S = (Q/8) K^T ----
        float sacc[8][4];
#pragma unroll
        for (int j = 0; j < 8; ++j)
#pragma unroll
            for (int q = 0; q < 4; ++q) sacc[j][q] = 0.0f;

#pragma unroll
        for (int ks = 0; ks < 4; ++ks) {
            uint32_t kh[4][4], kl[4][4];
#pragma unroll
            for (int n2 = 0; n2 < 4; ++n2) {
                const uint32_t off = (uint32_t)(n2 * 16 + lrow) * 128u
                                   + (((uint32_t)ks * 32u + lcol) ^ xr);
                ldsm_x4(kh[n2][0], kh[n2][1], kh[n2][2], kh[n2][3], st + off);
                ldsm_x4(kl[n2][0], kl[n2][1], kl[n2][2], kl[n2][3], st + 8192u + off);
            }
#pragma unroll
            for (int nj = 0; nj < 8; ++nj) {
                const int n2 = nj >> 1, h = nj & 1;
                mma_bf16(sacc[nj], qhi[ks], kh[n2][h], kh[n2][h + 2]);
                mma_bf16(sacc[nj], qhi[ks], kl[n2][h], kl[n2][h + 2]);
                mma_bf16(sacc[nj], qlo[ks], kh[n2][h], kh[n2][h + 2]);
            }
        }

        // ---- online softmax ----
        float mt0 = -1e30f, mt1 = -1e30f;
#pragma unroll
        for (int nj = 0; nj < 8; ++nj) {
            mt0 = fmaxf(mt0, fmaxf(sacc[nj][0], sacc[nj][1]));
            mt1 = fmaxf(mt1, fmaxf(sacc[nj][2], sacc[nj][3]));
        }
        mt0 = fmaxf(mt0, __shfl_xor_sync(0xffffffffu, mt0, 1));
        mt0 = fmaxf(mt0, __shfl_xor_sync(0xffffffffu, mt0, 2));
        mt1 = fmaxf(mt1, __shfl_xor_sync(0xffffffffu, mt1, 1));
        mt1 = fmaxf(mt1, __shfl_xor_sync(0xffffffffu, mt1, 2));
        const float mn0 = fmaxf(mr0, mt0);
        const float mn1 = fmaxf(mr1, mt1);
        const float cc0 = __expf(mr0 - mn0);
        const float cc1 = __expf(mr1 - mn1);
        mr0 = mn0; mr1 = mn1;
#pragma unroll
        for (int nj = 0; nj < 8; ++nj) {
            ctx[nj][0] *= cc0; ctx[nj][1] *= cc0;
            ctx[nj][2] *= cc1; ctx[nj][3] *= cc1;
        }

        // ---- P = exp(S - m) hi/lo + P·V ----
        float s0 = 0.0f, s1 = 0.0f;
#pragma unroll
        for (int kk = 0; kk < 4; ++kk) {
            uint32_t ahi[4], alo[4];
#pragma unroll
            for (int t2 = 0; t2 < 2; ++t2) {
                const int nj = 2 * kk + t2;
                const float p0 = __expf(sacc[nj][0] - mn0);
                const float p1 = __expf(sacc[nj][1] - mn0);
                const float p2 = __expf(sacc[nj][2] - mn1);
                const float p3 = __expf(sacc[nj][3] - mn1);
                s0 += p0 + p1; s1 += p2 + p3;
                const __nv_bfloat16 b0 = __float2bfloat16(p0);
                const __nv_bfloat16 b1 = __float2bfloat16(p1);
                const __nv_bfloat16 b2 = __float2bfloat16(p2);
                const __nv_bfloat16 b3 = __float2bfloat16(p3);
                ahi[2 * t2 + 0] = pack_bf(__bfloat162float(b0), __bfloat162float(b1));
                ahi[2 * t2 + 1] = pack_bf(__bfloat162float(b2), __bfloat162float(b3));
                alo[2 * t2 + 0] = pack_bf(p0 - __bfloat162float(b0), p1 - __bfloat162float(b1));
                alo[2 * t2 + 1] = pack_bf(p2 - __bfloat162float(b2), p3 - __bfloat162float(b3));
            }
            uint32_t vh[4][4], vl[4][4];
#pragma unroll
            for (int n2 = 0; n2 < 4; ++n2) {
                const uint32_t off = (uint32_t)(n2 * 16 + lrow) * 128u
                                   + (((uint32_t)kk * 32u + lcol) ^ xr);
                ldsm_x4(vh[n2][0], vh[n2][1], vh[n2][2], vh[n2][3], st + 16384u + off);
                ldsm_x4(vl[n2][0], vl[n2][1], vl[n2][2], vl[n2][3], st + 24576u + off);
            }
#pragma unroll
            for (int nj = 0; nj < 8; ++nj) {
                const int n2 = nj >> 1, h = nj & 1;
                mma_bf16(ctx[nj], ahi, vh[n2][h], vh[n2][h + 2]);
                mma_bf16(ctx[nj], ahi, vl[n2][h], vl[n2][h + 2]);
                mma_bf16(ctx[nj], alo, vh[n2][h], vh[n2][h + 2]);
            }
        }
        s0 += __shfl_xor_sync(0xffffffffu, s0, 1);
        s0 += __shfl_xor_sync(0xffffffffu, s0, 2);
        s1 += __shfl_xor_sync(0xffffffffu, s1, 1);
        s1 += __shfl_xor_sync(0xffffffffu, s1, 2);
        lr0 = lr0 * cc0 + s0;
        lr1 = lr1 * cc1 + s1;

        __syncthreads();
    }

    // ---- epilogue: normalize, write ctx as bf16 hi/lo into A slot 0 ----
    const float i0 = 1.0f / lr0;
    const float i1 = 1.0f / lr1;
    const int b  = bh >> 4;
    const int hh = bh & 15;
    const int gq = lane >> 2;
    const int tq = lane & 3;
    const int r0 = q0 + wid * 16 + gq;
    const int r1 = r0 + 8;
#pragma unroll
    for (int nj = 0; nj < 8; ++nj) {
        const int col = hh * 64 + nj * 8 + tq * 2;
        {
            const float v0 = ctx[nj][0] * i0;
            const float v1 = ctx[nj][1] * i0;
            const __nv_bfloat16 h0 = __float2bfloat16(v0);
            const __nv_bfloat16 h1 = __float2bfloat16(v1);
            const size_t idx = ((size_t)r0 * BATCH + b) * DMODEL + col;
            *(__nv_bfloat162*)&g_Ahi[idx] = __nv_bfloat162(h0, h1);
            *(__nv_bfloat162*)&g_Alo[idx] =
                __nv_bfloat162(__float2bfloat16(v0 - __bfloat162float(h0)),
                               __float2bfloat16(v1 - __bfloat162float(h1)));
        }
        {
            const float v0 = ctx[nj][2] * i1;
            const float v1 = ctx[nj][3] * i1;
            const __nv_bfloat16 h0 = __float2bfloat16(v0);
            const __nv_bfloat16 h1 = __float2bfloat16(v1);
            const size_t idx = ((size_t)r1 * BATCH + b) * DMODEL + col;
            *(__nv_bfloat162*)&g_Ahi[idx] = __nv_bfloat162(h0, h1);
            *(__nv_bfloat162*)&g_Alo[idx] =
                __nv_bfloat162(__float2bfloat16(v0 - __bfloat162float(h0)),
                               __float2bfloat16(v1 - __bfloat162float(h1)));
        }
    }
}

// ---------------------------------------------------------------------------
// kernel_launch
// order: query, key, value, time_decay, Wq, bq, Wk, bk, Wv, bv, Wo, bo
// ---------------------------------------------------------------------------
extern "C" void kernel_launch(void* const* d_in, const int* in_sizes, int n_in,
                              void* d_out, int out_size)
{
    const float* query      = (const float*)d_in[0];
    const float* key        = (const float*)d_in[1];
    const float* value      = (const float*)d_in[2];
    const float* time_decay = (const float*)d_in[3];
    const float* Wq = (const float*)d_in[4];
    const float* bq = (const float*)d_in[5];
    const float* Wk = (const float*)d_in[6];
    const float* bk = (const float*)d_in[7];
    const float* Wv = (const float*)d_in[8];
    const float* bv = (const float*)d_in[9];
    const float* Wo = (const float*)d_in[10];
    const float* bo = (const float*)d_in[11];
    float* out = (float*)d_out;

    cudaFuncSetAttribute(gemm_all, cudaFuncAttributeMaxDynamicSharedMemorySize, GEMM_SMEM_BYTES);
    cudaFuncSetAttribute(attn_mma, cudaFuncAttributeMaxDynamicSharedMemorySize, ATTN_SMEM_BYTES);

    // 1. all conversions (two launches)
    conv_w_all<<<dim3(1024, 4), 256>>>(Wq, Wk, Wv, Wo);
    conv_a_all<<<dim3(8192, 3), 256>>>(query, key, value);

    // 2. fused QKV projections (one launch, grid.z = 3)
    gemm_all<<<dim3(8, 64, 3), 256, GEMM_SMEM_BYTES>>>(bq, bk, bv, nullptr, nullptr, -1);

    // 3. attention
    attn_mma<<<dim3(T_LEN / 64, NBH), 128, ATTN_SMEM_BYTES>>>();

    // 4. output projection (+ time_decay)
    gemm_all<<<dim3(8, 64, 1), 256, GEMM_SMEM_BYTES>>>(bo, nullptr, nullptr, out, time_decay, 3);
}

// round 13
// speedup vs baseline: 3.6679x; 1.1305x over previous
#include <cuda_runtime.h>
#include <cuda_bf16.h>
#include <cuda_fp16.h>
#include <math.h>
#include <stdint.h>

#define T_LEN  2048
#define BATCH  4
#define DMODEL 1024
#define NHEAD  16
#define HDIM   64
#define MROWS  (T_LEN * BATCH)   // 8192
#define NBH    (BATCH * NHEAD)   // 64
#define QKV_ELEMS ((size_t)NBH * T_LEN * HDIM)

// ---------------------------------------------------------------------------
// Scratch ( __device__ globals: no allocation allowed )
// ---------------------------------------------------------------------------
__device__ __half g_Qh[QKV_ELEMS];                 // [bh][t][hd], prescaled 1/8 (single fp16)
__device__ __half g_Kh[QKV_ELEMS], g_Kl[QKV_ELEMS]; // [bh][t][hd], fp16 hi/lo
__device__ __half g_Vh[QKV_ELEMS], g_Vl[QKV_ELEMS]; // [bh][hd][t]  (TRANSPOSED), fp16 hi/lo

// slotted: A slots 0..2 = q/k/v inputs (slot 0 reused by attn output for O-proj)
__device__ __nv_bfloat16 g_Ahi[(size_t)3 * MROWS * DMODEL];
__device__ __nv_bfloat16 g_Alo[(size_t)3 * MROWS * DMODEL];
// W slots 0..3 = Wq, Wk, Wv, Wo
__device__ __nv_bfloat16 g_Whi[(size_t)4 * DMODEL * DMODEL];
__device__ __nv_bfloat16 g_Wlo[(size_t)4 * DMODEL * DMODEL];

// ---------------------------------------------------------------------------
// Primitives (compute_103-legal: mma.sync / ldmatrix / cp.async only)
// ---------------------------------------------------------------------------
__device__ __forceinline__ uint32_t smem_u32(const void* p) {
    uint32_t a;
    asm("{ .reg .u64 t; cvta.to.shared.u64 t, %1; cvt.u32.u64 %0, t; }"
        : "=r"(a) : "l"(p));
    return a;
}

__device__ __forceinline__ void ldsm_x4(uint32_t& r0, uint32_t& r1,
                                        uint32_t& r2, uint32_t& r3,
                                        uint32_t addr) {
    asm volatile("ldmatrix.sync.aligned.m8n8.x4.shared.b16 {%0,%1,%2,%3}, [%4];"
                 : "=r"(r0), "=r"(r1), "=r"(r2), "=r"(r3) : "r"(addr));
}

__device__ __forceinline__ void mma_bf16(float* d, const uint32_t* a,
                                         uint32_t b0, uint32_t b1) {
    asm volatile(
        "mma.sync.aligned.m16n8k16.row.col.f32.bf16.bf16.f32 "
        "{%0,%1,%2,%3}, {%4,%5,%6,%7}, {%8,%9}, {%0,%1,%2,%3};"
        : "+f"(d[0]), "+f"(d[1]), "+f"(d[2]), "+f"(d[3])
        : "r"(a[0]), "r"(a[1]), "r"(a[2]), "r"(a[3]), "r"(b0), "r"(b1));
}

__device__ __forceinline__ void mma_f16(float* d, const uint32_t* a,
                                        uint32_t b0, uint32_t b1) {
    asm volatile(
        "mma.sync.aligned.m16n8k16.row.col.f32.f16.f16.f32 "
        "{%0,%1,%2,%3}, {%4,%5,%6,%7}, {%8,%9}, {%0,%1,%2,%3};"
        : "+f"(d[0]), "+f"(d[1]), "+f"(d[2]), "+f"(d[3])
        : "r"(a[0]), "r"(a[1]), "r"(a[2]), "r"(a[3]), "r"(b0), "r"(b1));
}

// pack two fp32 -> f16x2 register (lo element in low half)
__device__ __forceinline__ uint32_t pack_h2(float lo_e, float hi_e) {
    uint32_t r;
    asm("cvt.rn.f16x2.f32 %0, %1, %2;" : "=r"(r) : "f"(hi_e), "f"(lo_e));
    return r;
}

__device__ __forceinline__ void cp16(uint32_t dst, const void* src) {
    asm volatile("cp.async.cg.shared.global [%0], [%1], 16;"
                 :: "r"(dst), "l"((uint64_t)__cvta_generic_to_global(src)));
}
#define CP_COMMIT() asm volatile("cp.async.commit_group;")
#define CP_WAIT(n)  asm volatile("cp.async.wait_group %0;" :: "n"(n))

// ---------------------------------------------------------------------------
// fp32 -> (bf16 hi, bf16 lo) split conversions, merged launches
// ---------------------------------------------------------------------------
__global__ void __launch_bounds__(256)
conv_a_all(const float* __restrict__ q, const float* __restrict__ k,
           const float* __restrict__ v)
{
    const int slot = blockIdx.y;
    const float* src = (slot == 0) ? q : (slot == 1) ? k : v;
    const size_t i = ((size_t)blockIdx.x * 256 + threadIdx.x) * 4;
    const size_t o = (size_t)slot * MROWS * DMODEL + i;
    const float4 x = *(const float4*)(src + i);
    __nv_bfloat16 h0 = __float2bfloat16(x.x);
    __nv_bfloat16 h1 = __float2bfloat16(x.y);
    __nv_bfloat16 h2 = __float2bfloat16(x.z);
    __nv_bfloat16 h3 = __float2bfloat16(x.w);
    *(__nv_bfloat162*)(g_Ahi + o)     = __nv_bfloat162(h0, h1);
    *(__nv_bfloat162*)(g_Ahi + o + 2) = __nv_bfloat162(h2, h3);
    *(__nv_bfloat162*)(g_Alo + o) =
        __nv_bfloat162(__float2bfloat16(x.x - __bfloat162float(h0)),
                       __float2bfloat16(x.y - __bfloat162float(h1)));
    *(__nv_bfloat162*)(g_Alo + o + 2) =
        __nv_bfloat162(__float2bfloat16(x.z - __bfloat162float(h2)),
                       __float2bfloat16(x.w - __bfloat162float(h3)));
}

__global__ void __launch_bounds__(256)
conv_w_all(const float* __restrict__ wq, const float* __restrict__ wk,
           const float* __restrict__ wv, const float* __restrict__ wo)
{
    const int slot = blockIdx.y;
    const float* src = (slot == 0) ? wq : (slot == 1) ? wk : (slot == 2) ? wv : wo;
    const size_t i = ((size_t)blockIdx.x * 256 + threadIdx.x) * 4;
    const size_t o = (size_t)slot * DMODEL * DMODEL + i;
    const float4 x = *(const float4*)(src + i);
    __nv_bfloat16 h0 = __float2bfloat16(x.x);
    __nv_bfloat16 h1 = __float2bfloat16(x.y);
    __nv_bfloat16 h2 = __float2bfloat16(x.z);
    __nv_bfloat16 h3 = __float2bfloat16(x.w);
    *(__nv_bfloat162*)(g_Whi + o)     = __nv_bfloat162(h0, h1);
    *(__nv_bfloat162*)(g_Whi + o + 2) = __nv_bfloat162(h2, h3);
    *(__nv_bfloat162*)(g_Wlo + o) =
        __nv_bfloat162(__float2bfloat16(x.x - __bfloat162float(h0)),
                       __float2bfloat16(x.y - __bfloat162float(h1)));
    *(__nv_bfloat162*)(g_Wlo + o + 2) =
        __nv_bfloat162(__float2bfloat16(x.z - __bfloat162float(h2)),
                       __float2bfloat16(x.w - __bfloat162float(h3)));
}

// ---------------------------------------------------------------------------
// bf16x3 GEMM, cp.async 3-stage pipeline, ONE syncthreads per K-chunk.
//   mode 0: Q -> g_Qh [bh][t][hd] fp16, scaled 1/8
//   mode 1: K -> g_Kh/g_Kl [bh][t][hd] fp16 hi/lo
//   mode 2: V -> g_Vh/g_Vl [bh][hd][t] fp16 hi/lo (transposed scatter)
//   mode 3: out = (C + bias) * time_decay (A = slot 0, W = slot 3)
// smem: 3 stages x {Ahi,Alo,Whi,Wlo tiles of 16KB} = 196608 B.
// ---------------------------------------------------------------------------
#define GEMM_SMEM_BYTES 196608

__device__ __forceinline__ void gemm_load_chunk(
    uint32_t sbase, uint32_t stage, int tid, int m0, int n0, int kt,
    const __nv_bfloat16* aHi, const __nv_bfloat16* aLo,
    const __nv_bfloat16* wHi, const __nv_bfloat16* wLo)
{
#pragma unroll
    for (int t4 = 0; t4 < 4; ++t4) {
        const __nv_bfloat16* src = (t4 == 0) ? aHi : (t4 == 1) ? aLo
                                 : (t4 == 2) ? wHi : wLo;
        const int rbase = (t4 < 2) ? m0 : n0;
#pragma unroll
        for (int i = 0; i < 4; ++i) {
            const int s   = tid + i * 256;
            const int row = s >> 3;
            const int chk = s & 7;
            const uint32_t so = stage + (uint32_t)t4 * 16384u + (uint32_t)row * 128u
                              + (((uint32_t)chk * 16u) ^ (((uint32_t)row & 7u) << 4));
            cp16(sbase + so, src + (size_t)(rbase + row) * DMODEL + kt + chk * 8);
        }
    }
}

__global__ void __launch_bounds__(256)
gemm_all(const float* __restrict__ b0, const float* __restrict__ b1,
         const float* __restrict__ b2, float* __restrict__ out,
         const float* __restrict__ td, int which)
{
    extern __shared__ __align__(128) char smem[];
    const uint32_t sbase = smem_u32(smem);

    const int mode = (which < 0) ? (int)blockIdx.z : which;
    const float* bias = (mode == 1) ? b1 : (mode == 2) ? b2 : b0;

    const size_t aoff = (mode < 3) ? (size_t)mode * MROWS * DMODEL : 0;
    const size_t woff = (size_t)mode * DMODEL * DMODEL;
    const __nv_bfloat16* aHi = g_Ahi + aoff;
    const __nv_bfloat16* aLo = g_Alo + aoff;
    const __nv_bfloat16* wHi = g_Whi + woff;
    const __nv_bfloat16* wLo = g_Wlo + woff;

    const int tid  = threadIdx.x;
    const int wid  = tid >> 5;
    const int lane = tid & 31;
    const int m0 = blockIdx.y * 128;
    const int n0 = blockIdx.x * 128;

    const int wm = (wid >> 1) * 32;
    const int wn = (wid & 1) * 64;

    const int sub = lane >> 3;
    const int r8  = lane & 7;
    const uint32_t xr = (uint32_t)r8 << 4;
    const int lrow_off = r8 + ((sub & 1) << 3);
    const uint32_t lcol_b = (uint32_t)((sub >> 1) << 4);

    float acc[2][8][4];
#pragma unroll
    for (int i = 0; i < 2; i++)
#pragma unroll
        for (int j = 0; j < 8; j++)
#pragma unroll
            for (int q = 0; q < 4; q++) acc[i][j][q] = 0.0f;

    gemm_load_chunk(sbase, 0, tid, m0, n0, 0, aHi, aLo, wHi, wLo);
    CP_COMMIT();
    gemm_load_chunk(sbase, 65536u, tid, m0, n0, 64, aHi, aLo, wHi, wLo);
    CP_COMMIT();

    for (int kc = 0; kc < 16; ++kc) {
        if (kc == 15) { CP_WAIT(0); } else { CP_WAIT(1); }
        __syncthreads();
        // safe: all warps finished reading stage (kc-1)%3 == (kc+2)%3
        if (kc < 14) {
            gemm_load_chunk(sbase, (uint32_t)((kc + 2) % 3) * 65536u, tid,
                            m0, n0, (kc + 2) * 64, aHi, aLo, wHi, wLo);
            CP_COMMIT();
        }

        const uint32_t st = sbase + (uint32_t)(kc % 3) * 65536u;
#pragma unroll
        for (int ks = 0; ks < 4; ++ks) {
            const uint32_t kb = (uint32_t)ks * 32u + lcol_b;

            uint32_t aHiF[2][4], aLoF[2][4], bHiF[4][4], bLoF[4][4];
#pragma unroll
            for (int mi = 0; mi < 2; ++mi) {
                const uint32_t row = (uint32_t)(wm + mi * 16 + lrow_off);
                const uint32_t off = row * 128u + (kb ^ xr);
                ldsm_x4(aHiF[mi][0], aHiF[mi][1], aHiF[mi][2], aHiF[mi][3], st + off);
                ldsm_x4(aLoF[mi][0], aLoF[mi][1], aLoF[mi][2], aLoF[mi][3], st + 16384u + off);
            }
#pragma unroll
            for (int nj2 = 0; nj2 < 4; ++nj2) {
                const uint32_t row = (uint32_t)(wn + nj2 * 16 + lrow_off);
                const uint32_t off = row * 128u + (kb ^ xr);
                ldsm_x4(bHiF[nj2][0], bHiF[nj2][1], bHiF[nj2][2], bHiF[nj2][3], st + 32768u + off);
                ldsm_x4(bLoF[nj2][0], bLoF[nj2][1], bLoF[nj2][2], bLoF[nj2][3], st + 49152u + off);
            }
#pragma unroll
            for (int mi = 0; mi < 2; ++mi)
#pragma unroll
                for (int nj = 0; nj < 8; ++nj) {
                    const int n2 = nj >> 1;
                    const int hi = nj & 1;
                    mma_bf16(acc[mi][nj], aHiF[mi], bHiF[n2][hi], bHiF[n2][hi + 2]);
                    mma_bf16(acc[mi][nj], aHiF[mi], bLoF[n2][hi], bLoF[n2][hi + 2]);
                    mma_bf16(acc[mi][nj], aLoF[mi], bHiF[n2][hi], bHiF[n2][hi + 2]);
                }
        }
    }

    // ---- epilogue ----
    const int gq = lane >> 2;
    const int tq = lane & 3;
#pragma unroll
    for (int mi = 0; mi < 2; ++mi) {
#pragma unroll
        for (int half = 0; half < 2; ++half) {
            const int m = m0 + wm + mi * 16 + gq + half * 8;
#pragma unroll
            for (int nj = 0; nj < 8; ++nj) {
                const int col = n0 + wn + nj * 8 + tq * 2;
                float v0 = acc[mi][nj][half * 2 + 0] + bias[col];
                float v1 = acc[mi][nj][half * 2 + 1] + bias[col + 1];
                if (mode == 3) {
                    const size_t idx = (size_t)m * DMODEL + col;
                    const float2 tv = *(const float2*)&td[idx];
                    *(float2*)&out[idx] = make_float2(v0 * tv.x, v1 * tv.y);
                } else {
                    const int trow = m >> 2;
                    const int b    = m & 3;
                    const int hh   = col >> 6;
                    const int hd   = col & 63;
                    if (mode == 0) {
                        const size_t base = ((size_t)(b * NHEAD + hh) * T_LEN + trow) * HDIM + hd;
                        *(__half2*)&g_Qh[base] = __floats2half2_rn(v0 * 0.125f, v1 * 0.125f);
                    } else if (mode == 1) {
                        const size_t base = ((size_t)(b * NHEAD + hh) * T_LEN + trow) * HDIM + hd;
                        const __half h0 = __float2half_rn(v0);
                        const __half h1 = __float2half_rn(v1);
                        *(__half2*)&g_Kh[base] = __halves2half2(h0, h1);
                        *(__half2*)&g_Kl[base] =
                            __floats2half2_rn(v0 - __half2float(h0), v1 - __half2float(h1));
                    } else {
                        const size_t base = ((size_t)(b * NHEAD + hh) * HDIM + hd) * T_LEN + trow;
                        const __half h0 = __float2half_rn(v0);
                        const __half h1 = __float2half_rn(v1);
                        g_Vh[base]         = h0;
                        g_Vh[base + T_LEN] = h1;
                        g_Vl[base]         = __float2half_rn(v0 - __half2float(h0));
                        g_Vl[base + T_LEN] = __float2half_rn(v1 - __half2float(h1));
                    }
                }
            }
        }
    }
}

// ---------------------------------------------------------------------------
// Flash attention, fp16 one-sided-corrected:
//   S = Q_f16 · (K_hi + K_lo)   (2 passes)
//   O = P_f16 · (V_hi + V_lo)   (2 passes)
// CTA: 128 threads (4 warps), 64 q-rows. smem: 2 stages x 32KB
// {Kh,Kl,Vh,Vl @ +0/+8K/+16K/+24K}; Q (hi only) staged through stage 1.
// Output -> bf16 hi/lo into g_Ahi/g_Alo slot 0 (O-proj A operand).
// ---------------------------------------------------------------------------
#define ATTN_SMEM_BYTES 65536

__device__ __forceinline__ void attn_load_chunk(
    uint32_t sbase, uint32_t stage, int tid, int kt,
    size_t baseRM, size_t baseVT)
{
#pragma unroll
    for (int i = 0; i < 4; ++i) {
        const int s = tid + i * 128;
        const int row = s >> 3, c16 = s & 7;
        const uint32_t so = stage + (uint32_t)row * 128u
            + (((uint32_t)c16 * 16u) ^ (((uint32_t)row & 7u) << 4));
        const size_t gk = baseRM + (size_t)(kt + row) * HDIM + c16 * 8;
        const size_t gv = baseVT + (size_t)row * T_LEN + kt + c16 * 8;
        cp16(sbase + so,          g_Kh + gk);
        cp16(sbase + 8192u + so,  g_Kl + gk);
        cp16(sbase + 16384u + so, g_Vh + gv);
        cp16(sbase + 24576u + so, g_Vl + gv);
    }
}

__global__ void __launch_bounds__(128)
attn_mma()
{
    extern __shared__ __align__(1024) char sm[];
    const uint32_t sb = smem_u32(sm);

    const int tid  = threadIdx.x;
    const int wid  = tid >> 5;
    const int lane = tid & 31;
    const int bh   = blockIdx.y;
    const int q0   = blockIdx.x * 64;
    const size_t baseRM = (size_t)bh * T_LEN * HDIM;
    const size_t baseVT = (size_t)bh * HDIM * T_LEN;

    const int sub = lane >> 3;
    const int r8  = lane & 7;
    const uint32_t xr = (uint32_t)r8 << 4;
    const int lrow = r8 + ((sub & 1) << 3);
    const uint32_t lcol = (uint32_t)((sub >> 1) << 4);

    // ---- prologue: chunk0 -> stage0; Q(hi) -> stage1 area ----
    attn_load_chunk(sb, 0, tid, 0, baseRM, baseVT);
    CP_COMMIT();
#pragma unroll
    for (int i = 0; i < 4; ++i) {
        const int s = tid + i * 128;
        const int row = s >> 3, c16 = s & 7;
        const uint32_t so = (uint32_t)row * 128u
            + (((uint32_t)c16 * 16u) ^ (((uint32_t)row & 7u) << 4));
        cp16(sb + 32768u + so, g_Qh + baseRM + (size_t)(q0 + row) * HDIM + c16 * 8);
    }
    CP_COMMIT();
    CP_WAIT(0);
    __syncthreads();

    uint32_t qh[4][4];
    {
        const uint32_t qrow = (uint32_t)(wid * 16 + lrow);
#pragma unroll
        for (int ks = 0; ks < 4; ++ks) {
            const uint32_t off = qrow * 128u + (((uint32_t)ks * 32u + lcol) ^ xr);
            ldsm_x4(qh[ks][0], qh[ks][1], qh[ks][2], qh[ks][3], sb + 32768u + off);
        }
    }
    __syncthreads();   // stage1 free for chunk1

    float ctx[8][4];
#pragma unroll
    for (int j = 0; j < 8; ++j)
#pragma unroll
        for (int q = 0; q < 4; ++q) ctx[j][q] = 0.0f;
    float mr0 = -1e30f, mr1 = -1e30f, lr0 = 0.0f, lr1 = 0.0f;

    for (int c = 0; c < T_LEN / 64; ++c) {
        if (c < T_LEN / 64 - 1) {
            attn_load_chunk(sb, (uint32_t)((c + 1) & 1) * 32768u, tid,
                            (c + 1) * 64, baseRM, baseVT);
            CP_COMMIT();
            CP_WAIT(1);
        } else {
            CP_WAIT(0);
        }
        __syncthreads();

        const uint32_t st = sb + (uint32_t)(c & 1) * 32768u;

        // ---- S = Q (Khi + Klo) ----
        float sacc[8][4];
#pragma unroll
        for (int j = 0; j < 8; ++j)
#pragma unroll
            for (int q = 0; q < 4; ++q) sacc[j][q] = 0.0f;

#pragma unroll
        for (int ks = 0; ks < 4; ++ks) {
            uint32_t kh[4][4], kl[4][4];
#pragma unroll
            for (int n2 = 0; n2 < 4; ++n2) {
                const uint32_t off = (uint32_t)(n2 * 16 + lrow) * 128u
                                   + (((uint32_t)ks * 32u + lcol) ^ xr);
                ldsm_x4(kh[n2][0], kh[n2][1], kh[n2][2], kh[n2][3], st + off);
                ldsm_x4(kl[n2][0], kl[n2][1], kl[n2][2], kl[n2][3], st + 8192u + off);
            }
#pragma unroll
            for (int nj = 0; nj < 8; ++nj) {
                const int n2 = nj >> 1, h = nj & 1;
                mma_f16(sacc[nj], qh[ks], kh[n2][h], kh[n2][h + 2]);
                mma_f16(sacc[nj], qh[ks], kl[n2][h], kl[n2][h + 2]);
            }
        }

        // ---- online softmax ----
        float mt0 = -1e30f, mt1 = -1e30f;
#pragma unroll
        for (int nj = 0; nj < 8; ++nj) {
            mt0 = fmaxf(mt0, fmaxf(sacc[nj][0], sacc[nj][1]));
            mt1 = fmaxf(mt1, fmaxf(sacc[nj][2], sacc[nj][3]));
        }
        mt0 = fmaxf(mt0, __shfl_xor_sync(0xffffffffu, mt0, 1));
        mt0 = fmaxf(mt0, __shfl_xor_sync(0xffffffffu, mt0, 2));
        mt1 = fmaxf(mt1, __shfl_xor_sync(0xffffffffu, mt1, 1));
        mt1 = fmaxf(mt1, __shfl_xor_sync(0xffffffffu, mt1, 2));
        const float mn0 = fmaxf(mr0, mt0);
        const float mn1 = fmaxf(mr1, mt1);
        const float cc0 = __expf(mr0 - mn0);
        const float cc1 = __expf(mr1 - mn1);
        mr0 = mn0; mr1 = mn1;
#pragma unroll
        for (int nj = 0; nj < 8; ++nj) {
            ctx[nj][0] *= cc0; ctx[nj][1] *= cc0;
            ctx[nj][2] *= cc1; ctx[nj][3] *= cc1;
        }

        // ---- P = exp(S - m) (fp16) + P (Vhi + Vlo) ----
        float s0 = 0.0f, s1 = 0.0f;
#pragma unroll
        for (int kk = 0; kk < 4; ++kk) {
            uint32_t ah[4];
#pragma unroll
            for (int t2 = 0; t2 < 2; ++t2) {
                const int nj = 2 * kk + t2;
                const float p0 = __expf(sacc[nj][0] - mn0);
                const float p1 = __expf(sacc[nj][1] - mn0);
                const float p2 = __expf(sacc[nj][2] - mn1);
                const float p3 = __expf(sacc[nj][3] - mn1);
                s0 += p0 + p1; s1 += p2 + p3;
                ah[2 * t2 + 0] = pack_h2(p0, p1);
                ah[2 * t2 + 1] = pack_h2(p2, p3);
            }
            uint32_t vh[4][4], vl[4][4];
#pragma unroll
            for (int n2 = 0; n2 < 4; ++n2) {
                const uint32_t off = (uint32_t)(n2 * 16 + lrow) * 128u
                                   + (((uint32_t)kk * 32u + lcol) ^ xr);
                ldsm_x4(vh[n2][0], vh[n2][1], vh[n2][2], vh[n2][3], st + 16384u + off);
                ldsm_x4(vl[n2][0], vl[n2][1], vl[n2][2], vl[n2][3], st + 24576u + off);
            }
#pragma unroll
            for (int nj = 0; nj < 8; ++nj) {
                const int n2 = nj >> 1, h = nj & 1;
                mma_f16(ctx[nj], ah, vh[n2][h], vh[n2][h + 2]);
                mma_f16(ctx[nj], ah, vl[n2][h], vl[n2][h + 2]);
            }
        }
        s0 += __shfl_xor_sync(0xffffffffu, s0, 1);
        s0 += __shfl_xor_sync(0xffffffffu, s0, 2);
        s1 += __shfl_xor_sync(0xffffffffu, s1, 1);
        s1 += __shfl_xor_sync(0xffffffffu, s1, 2);
        lr0 = lr0 * cc0 + s0;
        lr1 = lr1 * cc1 + s1;

        __syncthreads();
    }

    // ---- epilogue: normalize, write ctx as bf16 hi/lo into A slot 0 ----
    const float i0 = 1.0f / lr0;
    const float i1 = 1.0f / lr1;
    const int b  = bh >> 4;
    const int hh = bh & 15;
    const int gq = lane >> 2;
    const int tq = lane & 3;
    const int r0 = q0 + wid * 16 + gq;
    const int r1 = r0 + 8;
#pragma unroll
    for (int nj = 0; nj < 8; ++nj) {
        const int col = hh * 64 + nj * 8 + tq * 2;
        {
            const float v0 = ctx[nj][0] * i0;
            const float v1 = ctx[nj][1] * i0;
            const __nv_bfloat16 h0 = __float2bfloat16(v0);
            const __nv_bfloat16 h1 = __float2bfloat16(v1);
            const size_t idx = ((size_t)r0 * BATCH + b) * DMODEL + col;
            *(__nv_bfloat162*)&g_Ahi[idx] = __nv_bfloat162(h0, h1);
            *(__nv_bfloat162*)&g_Alo[idx] =
                __nv_bfloat162(__float2bfloat16(v0 - __bfloat162float(h0)),
                               __float2bfloat16(v1 - __bfloat162float(h1)));
        }
        {
            const float v0 = ctx[nj][2] * i1;
            const float v1 = ctx[nj][3] * i1;
            const __nv_bfloat16 h0 = __float2bfloat16(v0);
            const __nv_bfloat16 h1 = __float2bfloat16(v1);
            const size_t idx = ((size_t)r1 * BATCH + b) * DMODEL + col;
            *(__nv_bfloat162*)&g_Ahi[idx] = __nv_bfloat162(h0, h1);
            *(__nv_bfloat162*)&g_Alo[idx] =
                __nv_bfloat162(__float2bfloat16(v0 - __bfloat162float(h0)),
                               __float2bfloat16(v1 - __bfloat162float(h1)));
        }
    }
}

// ---------------------------------------------------------------------------
// kernel_launch
// order: query, key, value, time_decay, Wq, bq, Wk, bk, Wv, bv, Wo, bo
// ---------------------------------------------------------------------------
extern "C" void kernel_launch(void* const* d_in, const int* in_sizes, int n_in,
                              void* d_out, int out_size)
{
    const float* query      = (const float*)d_in[0];
    const float* key        = (const float*)d_in[1];
    const float* value      = (const float*)d_in[2];
    const float* time_decay = (const float*)d_in[3];
    const float* Wq = (const float*)d_in[4];
    const float* bq = (const float*)d_in[5];
    const float* Wk = (const float*)d_in[6];
    const float* bk = (const float*)d_in[7];
    const float* Wv = (const float*)d_in[8];
    const float* bv = (const float*)d_in[9];
    const float* Wo = (const float*)d_in[10];
    const float* bo = (const float*)d_in[11];
    float* out = (float*)d_out;

    cudaFuncSetAttribute(gemm_all, cudaFuncAttributeMaxDynamicSharedMemorySize, GEMM_SMEM_BYTES);
    cudaFuncSetAttribute(attn_mma, cudaFuncAttributeMaxDynamicSharedMemorySize, ATTN_SMEM_BYTES);

    // 1. all conversions (two launches)
    conv_w_all<<<dim3(1024, 4), 256>>>(Wq, Wk, Wv, Wo);
    conv_a_all<<<dim3(8192, 3), 256>>>(query, key, value);

    // 2. fused QKV projections (one launch, grid.z = 3)
    gemm_all<<<dim3(8, 64, 3), 256, GEMM_SMEM_BYTES>>>(bq, bk, bv, nullptr, nullptr, -1);

    // 3. attention
    attn_mma<<<dim3(T_LEN / 64, NBH), 128, ATTN_SMEM_BYTES>>>();

    // 4. output projection (+ time_decay)
    gemm_all<<<dim3(8, 64, 1), 256, GEMM_SMEM_BYTES>>>(bo, nullptr, nullptr, out, time_decay, 3);
}

// round 14
// speedup vs baseline: 4.9860x; 1.3594x over previous
#include <cuda_runtime.h>
#include <cuda_bf16.h>
#include <cuda_fp16.h>
#include <math.h>
#include <stdint.h>

#define T_LEN  2048
#define BATCH  4
#define DMODEL 1024
#define NHEAD  16
#define HDIM   64
#define MROWS  (T_LEN * BATCH)   // 8192
#define NBH    (BATCH * NHEAD)   // 64
#define QKV_ELEMS ((size_t)NBH * T_LEN * HDIM)

// ---------------------------------------------------------------------------
// Scratch ( __device__ globals: no allocation allowed )
// ---------------------------------------------------------------------------
__device__ __half g_Qh[QKV_ELEMS];                  // [bh][t][hd], prescaled 1/8
__device__ __half g_Kh[QKV_ELEMS], g_Kl[QKV_ELEMS]; // [bh][t][hd], fp16 hi/lo
__device__ __half g_Vh[QKV_ELEMS], g_Vl[QKV_ELEMS]; // [bh][hd][t] (TRANSPOSED), fp16 hi/lo

// A slots 0..2 = q/k/v inputs (slot 0 reused by attn output for O-proj); fp16 single
__device__ __half g_Af[(size_t)3 * MROWS * DMODEL];
// W slots 0..3 = Wq, Wk, Wv, Wo; fp16 hi/lo split
__device__ __half g_Wh16[(size_t)4 * DMODEL * DMODEL];
__device__ __half g_Wl16[(size_t)4 * DMODEL * DMODEL];

// ---------------------------------------------------------------------------
// Primitives (compute_103-legal: mma.sync / ldmatrix / cp.async only)
// ---------------------------------------------------------------------------
__device__ __forceinline__ uint32_t smem_u32(const void* p) {
    uint32_t a;
    asm("{ .reg .u64 t; cvta.to.shared.u64 t, %1; cvt.u32.u64 %0, t; }"
        : "=r"(a) : "l"(p));
    return a;
}

__device__ __forceinline__ void ldsm_x4(uint32_t& r0, uint32_t& r1,
                                        uint32_t& r2, uint32_t& r3,
                                        uint32_t addr) {
    asm volatile("ldmatrix.sync.aligned.m8n8.x4.shared.b16 {%0,%1,%2,%3}, [%4];"
                 : "=r"(r0), "=r"(r1), "=r"(r2), "=r"(r3) : "r"(addr));
}

__device__ __forceinline__ void mma_f16(float* d, const uint32_t* a,
                                        uint32_t b0, uint32_t b1) {
    asm volatile(
        "mma.sync.aligned.m16n8k16.row.col.f32.f16.f16.f32 "
        "{%0,%1,%2,%3}, {%4,%5,%6,%7}, {%8,%9}, {%0,%1,%2,%3};"
        : "+f"(d[0]), "+f"(d[1]), "+f"(d[2]), "+f"(d[3])
        : "r"(a[0]), "r"(a[1]), "r"(a[2]), "r"(a[3]), "r"(b0), "r"(b1));
}

// pack two fp32 -> f16x2 register (lo element in low half)
__device__ __forceinline__ uint32_t pack_h2(float lo_e, float hi_e) {
    uint32_t r;
    asm("cvt.rn.f16x2.f32 %0, %1, %2;" : "=r"(r) : "f"(hi_e), "f"(lo_e));
    return r;
}

__device__ __forceinline__ void cp16(uint32_t dst, const void* src) {
    asm volatile("cp.async.cg.shared.global [%0], [%1], 16;"
                 :: "r"(dst), "l"((uint64_t)__cvta_generic_to_global(src)));
}
#define CP_COMMIT() asm volatile("cp.async.commit_group;")
#define CP_WAIT(n)  asm volatile("cp.async.wait_group %0;" :: "n"(n))

// ---------------------------------------------------------------------------
// Conversions: activations -> fp16 single; weights -> fp16 hi/lo
// ---------------------------------------------------------------------------
__global__ void __launch_bounds__(256)
conv_a_all(const float* __restrict__ q, const float* __restrict__ k,
           const float* __restrict__ v)
{
    const int slot = blockIdx.y;
    const float* src = (slot == 0) ? q : (slot == 1) ? k : v;
    const size_t i = ((size_t)blockIdx.x * 256 + threadIdx.x) * 4;
    const size_t o = (size_t)slot * MROWS * DMODEL + i;
    const float4 x = *(const float4*)(src + i);
    *(__half2*)(g_Af + o)     = __floats2half2_rn(x.x, x.y);
    *(__half2*)(g_Af + o + 2) = __floats2half2_rn(x.z, x.w);
}

__global__ void __launch_bounds__(256)
conv_w_all(const float* __restrict__ wq, const float* __restrict__ wk,
           const float* __restrict__ wv, const float* __restrict__ wo)
{
    const int slot = blockIdx.y;
    const float* src = (slot == 0) ? wq : (slot == 1) ? wk : (slot == 2) ? wv : wo;
    const size_t i = ((size_t)blockIdx.x * 256 + threadIdx.x) * 4;
    const size_t o = (size_t)slot * DMODEL * DMODEL + i;
    const float4 x = *(const float4*)(src + i);
    const __half h0 = __float2half_rn(x.x);
    const __half h1 = __float2half_rn(x.y);
    const __half h2 = __float2half_rn(x.z);
    const __half h3 = __float2half_rn(x.w);
    *(__half2*)(g_Wh16 + o)     = __halves2half2(h0, h1);
    *(__half2*)(g_Wh16 + o + 2) = __halves2half2(h2, h3);
    *(__half2*)(g_Wl16 + o) =
        __floats2half2_rn(x.x - __half2float(h0), x.y - __half2float(h1));
    *(__half2*)(g_Wl16 + o + 2) =
        __floats2half2_rn(x.z - __half2float(h2), x.w - __half2float(h3));
}

// ---------------------------------------------------------------------------
// fp16 one-sided GEMM: C = A_f16 @ (W_hi + W_lo)^T  (2 MMA passes)
//   mode 0: Q -> g_Qh [bh][t][hd] fp16, scaled 1/8
//   mode 1: K -> g_Kh/g_Kl [bh][t][hd] fp16 hi/lo
//   mode 2: V -> g_Vh/g_Vl [bh][hd][t] fp16 hi/lo (transposed scatter)
//   mode 3: out = (C + bias) * time_decay (A = slot 0, W = slot 3)
// smem: 2 stages x {A, Whi, Wlo tiles of 16KB} = 98304 B -> 2 CTAs/SM.
// ---------------------------------------------------------------------------
#define GEMM_SMEM_BYTES 98304

__device__ __forceinline__ void gemm_load_chunk(
    uint32_t sbase, uint32_t stage, int tid, int m0, int n0, int kt,
    const __half* aF, const __half* wHi, const __half* wLo)
{
#pragma unroll
    for (int t3 = 0; t3 < 3; ++t3) {
        const __half* src = (t3 == 0) ? aF : (t3 == 1) ? wHi : wLo;
        const int rbase = (t3 == 0) ? m0 : n0;
#pragma unroll
        for (int i = 0; i < 4; ++i) {
            const int s   = tid + i * 256;
            const int row = s >> 3;
            const int chk = s & 7;
            const uint32_t so = stage + (uint32_t)t3 * 16384u + (uint32_t)row * 128u
                              + (((uint32_t)chk * 16u) ^ (((uint32_t)row & 7u) << 4));
            cp16(sbase + so, src + (size_t)(rbase + row) * DMODEL + kt + chk * 8);
        }
    }
}

__global__ void __launch_bounds__(256, 2)
gemm_all(const float* __restrict__ b0, const float* __restrict__ b1,
         const float* __restrict__ b2, float* __restrict__ out,
         const float* __restrict__ td, int which)
{
    extern __shared__ __align__(128) char smem[];
    const uint32_t sbase = smem_u32(smem);

    const int mode = (which < 0) ? (int)blockIdx.z : which;
    const float* bias = (mode == 1) ? b1 : (mode == 2) ? b2 : b0;

    const size_t aoff = (mode < 3) ? (size_t)mode * MROWS * DMODEL : 0;
    const size_t woff = (size_t)mode * DMODEL * DMODEL;
    const __half* aF  = g_Af   + aoff;
    const __half* wHi = g_Wh16 + woff;
    const __half* wLo = g_Wl16 + woff;

    const int tid  = threadIdx.x;
    const int wid  = tid >> 5;
    const int lane = tid & 31;
    const int m0 = blockIdx.y * 128;
    const int n0 = blockIdx.x * 128;

    const int wm = (wid >> 1) * 32;
    const int wn = (wid & 1) * 64;

    const int sub = lane >> 3;
    const int r8  = lane & 7;
    const uint32_t xr = (uint32_t)r8 << 4;
    const int lrow_off = r8 + ((sub & 1) << 3);
    const uint32_t lcol_b = (uint32_t)((sub >> 1) << 4);

    float acc[2][8][4];
#pragma unroll
    for (int i = 0; i < 2; i++)
#pragma unroll
        for (int j = 0; j < 8; j++)
#pragma unroll
            for (int q = 0; q < 4; q++) acc[i][j][q] = 0.0f;

    gemm_load_chunk(sbase, 0, tid, m0, n0, 0, aF, wHi, wLo);
    CP_COMMIT();

    for (int kc = 0; kc < 16; ++kc) {
        if (kc < 15) {
            gemm_load_chunk(sbase, (uint32_t)((kc + 1) & 1) * 49152u, tid,
                            m0, n0, (kc + 1) * 64, aF, wHi, wLo);
            CP_COMMIT();
            CP_WAIT(1);
        } else {
            CP_WAIT(0);
        }
        __syncthreads();

        const uint32_t st = sbase + (uint32_t)(kc & 1) * 49152u;
#pragma unroll
        for (int ks = 0; ks < 4; ++ks) {
            const uint32_t kb = (uint32_t)ks * 32u + lcol_b;

            uint32_t aFr[2][4], wHiF[4][4], wLoF[4][4];
#pragma unroll
            for (int mi = 0; mi < 2; ++mi) {
                const uint32_t row = (uint32_t)(wm + mi * 16 + lrow_off);
                const uint32_t off = row * 128u + (kb ^ xr);
                ldsm_x4(aFr[mi][0], aFr[mi][1], aFr[mi][2], aFr[mi][3], st + off);
            }
#pragma unroll
            for (int nj2 = 0; nj2 < 4; ++nj2) {
                const uint32_t row = (uint32_t)(wn + nj2 * 16 + lrow_off);
                const uint32_t off = row * 128u + (kb ^ xr);
                ldsm_x4(wHiF[nj2][0], wHiF[nj2][1], wHiF[nj2][2], wHiF[nj2][3], st + 16384u + off);
                ldsm_x4(wLoF[nj2][0], wLoF[nj2][1], wLoF[nj2][2], wLoF[nj2][3], st + 32768u + off);
            }
#pragma unroll
            for (int mi = 0; mi < 2; ++mi)
#pragma unroll
                for (int nj = 0; nj < 8; ++nj) {
                    const int n2 = nj >> 1;
                    const int hi = nj & 1;
                    mma_f16(acc[mi][nj], aFr[mi], wHiF[n2][hi], wHiF[n2][hi + 2]);
                    mma_f16(acc[mi][nj], aFr[mi], wLoF[n2][hi], wLoF[n2][hi + 2]);
                }
        }
        __syncthreads();
    }

    // ---- epilogue ----
    const int gq = lane >> 2;
    const int tq = lane & 3;
#pragma unroll
    for (int mi = 0; mi < 2; ++mi) {
#pragma unroll
        for (int half = 0; half < 2; ++half) {
            const int m = m0 + wm + mi * 16 + gq + half * 8;
#pragma unroll
            for (int nj = 0; nj < 8; ++nj) {
                const int col = n0 + wn + nj * 8 + tq * 2;
                float v0 = acc[mi][nj][half * 2 + 0] + bias[col];
                float v1 = acc[mi][nj][half * 2 + 1] + bias[col + 1];
                if (mode == 3) {
                    const size_t idx = (size_t)m * DMODEL + col;
                    const float2 tv = *(const float2*)&td[idx];
                    *(float2*)&out[idx] = make_float2(v0 * tv.x, v1 * tv.y);
                } else {
                    const int trow = m >> 2;
                    const int b    = m & 3;
                    const int hh   = col >> 6;
                    const int hd   = col & 63;
                    if (mode == 0) {
                        const size_t base = ((size_t)(b * NHEAD + hh) * T_LEN + trow) * HDIM + hd;
                        *(__half2*)&g_Qh[base] = __floats2half2_rn(v0 * 0.125f, v1 * 0.125f);
                    } else if (mode == 1) {
                        const size_t base = ((size_t)(b * NHEAD + hh) * T_LEN + trow) * HDIM + hd;
                        const __half h0 = __float2half_rn(v0);
                        const __half h1 = __float2half_rn(v1);
                        *(__half2*)&g_Kh[base] = __halves2half2(h0, h1);
                        *(__half2*)&g_Kl[base] =
                            __floats2half2_rn(v0 - __half2float(h0), v1 - __half2float(h1));
                    } else {
                        const size_t base = ((size_t)(b * NHEAD + hh) * HDIM + hd) * T_LEN + trow;
                        const __half h0 = __float2half_rn(v0);
                        const __half h1 = __float2half_rn(v1);
                        g_Vh[base]         = h0;
                        g_Vh[base + T_LEN] = h1;
                        g_Vl[base]         = __float2half_rn(v0 - __half2float(h0));
                        g_Vl[base + T_LEN] = __float2half_rn(v1 - __half2float(h1));
                    }
                }
            }
        }
    }
}

// ---------------------------------------------------------------------------
// Flash attention, fp16 one-sided-corrected (unchanged from R13):
//   S = Q_f16 · (K_hi + K_lo)   (2 passes)
//   O = P_f16 · (V_hi + V_lo)   (2 passes)
// CTA: 128 threads (4 warps), 64 q-rows. smem: 2 stages x 32KB
// {Kh,Kl,Vh,Vl @ +0/+8K/+16K/+24K}; Q (hi only) staged through stage 1.
// Output -> fp16 into g_Af slot 0 (O-proj A operand).
// ---------------------------------------------------------------------------
#define ATTN_SMEM_BYTES 65536

__device__ __forceinline__ void attn_load_chunk(
    uint32_t sbase, uint32_t stage, int tid, int kt,
    size_t baseRM, size_t baseVT)
{
#pragma unroll
    for (int i = 0; i < 4; ++i) {
        const int s = tid + i * 128;
        const int row = s >> 3, c16 = s & 7;
        const uint32_t so = stage + (uint32_t)row * 128u
            + (((uint32_t)c16 * 16u) ^ (((uint32_t)row & 7u) << 4));
        const size_t gk = baseRM + (size_t)(kt + row) * HDIM + c16 * 8;
        const size_t gv = baseVT + (size_t)row * T_LEN + kt + c16 * 8;
        cp16(sbase + so,          g_Kh + gk);
        cp16(sbase + 8192u + so,  g_Kl + gk);
        cp16(sbase + 16384u + so, g_Vh + gv);
        cp16(sbase + 24576u + so, g_Vl + gv);
    }
}

__global__ void __launch_bounds__(128)
attn_mma()
{
    extern __shared__ __align__(1024) char sm[];
    const uint32_t sb = smem_u32(sm);

    const int tid  = threadIdx.x;
    const int wid  = tid >> 5;
    const int lane = tid & 31;
    const int bh   = blockIdx.y;
    const int q0   = blockIdx.x * 64;
    const size_t baseRM = (size_t)bh * T_LEN * HDIM;
    const size_t baseVT = (size_t)bh * HDIM * T_LEN;

    const int sub = lane >> 3;
    const int r8  = lane & 7;
    const uint32_t xr = (uint32_t)r8 << 4;
    const int lrow = r8 + ((sub & 1) << 3);
    const uint32_t lcol = (uint32_t)((sub >> 1) << 4);

    // ---- prologue: chunk0 -> stage0; Q -> stage1 area ----
    attn_load_chunk(sb, 0, tid, 0, baseRM, baseVT);
    CP_COMMIT();
#pragma unroll
    for (int i = 0; i < 4; ++i) {
        const int s = tid + i * 128;
        const int row = s >> 3, c16 = s & 7;
        const uint32_t so = (uint32_t)row * 128u
            + (((uint32_t)c16 * 16u) ^ (((uint32_t)row & 7u) << 4));
        cp16(sb + 32768u + so, g_Qh + baseRM + (size_t)(q0 + row) * HDIM + c16 * 8);
    }
    CP_COMMIT();
    CP_WAIT(0);
    __syncthreads();

    uint32_t qh[4][4];
    {
        const uint32_t qrow = (uint32_t)(wid * 16 + lrow);
#pragma unroll
        for (int ks = 0; ks < 4; ++ks) {
            const uint32_t off = qrow * 128u + (((uint32_t)ks * 32u + lcol) ^ xr);
            ldsm_x4(qh[ks][0], qh[ks][1], qh[ks][2], qh[ks][3], sb + 32768u + off);
        }
    }
    __syncthreads();   // stage1 free for chunk1

    float ctx[8][4];
#pragma unroll
    for (int j = 0; j < 8; ++j)
#pragma unroll
        for (int q = 0; q < 4; ++q) ctx[j][q] = 0.0f;
    float mr0 = -1e30f, mr1 = -1e30f, lr0 = 0.0f, lr1 = 0.0f;

    for (int c = 0; c < T_LEN / 64; ++c) {
        if (c < T_LEN / 64 - 1) {
            attn_load_chunk(sb, (uint32_t)((c + 1) & 1) * 32768u, tid,
                            (c + 1) * 64, baseRM, baseVT);
            CP_COMMIT();
            CP_WAIT(1);
        } else {
            CP_WAIT(0);
        }
        __syncthreads();

        const uint32_t st = sb + (uint32_t)(c & 1) * 32768u;

        // ---- S = Q (Khi + Klo) ----
        float sacc[8][4];
#pragma unroll
        for (int j = 0; j < 8; ++j)
#pragma unroll
            for (int q = 0; q < 4; ++q) sacc[j][q] = 0.0f;

#pragma unroll
        for (int ks = 0; ks < 4; ++ks) {
            uint32_t kh[4][4], kl[4][4];
#pragma unroll
            for (int n2 = 0; n2 < 4; ++n2) {
                const uint32_t off = (uint32_t)(n2 * 16 + lrow) * 128u
                                   + (((uint32_t)ks * 32u + lcol) ^ xr);
                ldsm_x4(kh[n2][0], kh[n2][1], kh[n2][2], kh[n2][3], st + off);
                ldsm_x4(kl[n2][0], kl[n2][1], kl[n2][2], kl[n2][3], st + 8192u + off);
            }
#pragma unroll
            for (int nj = 0; nj < 8; ++nj) {
                const int n2 = nj >> 1, h = nj & 1;
                mma_f16(sacc[nj], qh[ks], kh[n2][h], kh[n2][h + 2]);
                mma_f16(sacc[nj], qh[ks], kl[n2][h], kl[n2][h + 2]);
            }
        }

        // ---- online softmax ----
        float mt0 = -1e30f, mt1 = -1e30f;
#pragma unroll
        for (int nj = 0; nj < 8; ++nj) {
            mt0 = fmaxf(mt0, fmaxf(sacc[nj][0], sacc[nj][1]));
            mt1 = fmaxf(mt1, fmaxf(sacc[nj][2], sacc[nj][3]));
        }
        mt0 = fmaxf(mt0, __shfl_xor_sync(0xffffffffu, mt0, 1));
        mt0 = fmaxf(mt0, __shfl_xor_sync(0xffffffffu, mt0, 2));
        mt1 = fmaxf(mt1, __shfl_xor_sync(0xffffffffu, mt1, 1));
        mt1 = fmaxf(mt1, __shfl_xor_sync(0xffffffffu, mt1, 2));
        const float mn0 = fmaxf(mr0, mt0);
        const float mn1 = fmaxf(mr1, mt1);
        const float cc0 = __expf(mr0 - mn0);
        const float cc1 = __expf(mr1 - mn1);
        mr0 = mn0; mr1 = mn1;
#pragma unroll
        for (int nj = 0; nj < 8; ++nj) {
            ctx[nj][0] *= cc0; ctx[nj][1] *= cc0;
            ctx[nj][2] *= cc1; ctx[nj][3] *= cc1;
        }

        // ---- P = exp(S - m) (fp16) + P (Vhi + Vlo) ----
        float s0 = 0.0f, s1 = 0.0f;
#pragma unroll
        for (int kk = 0; kk < 4; ++kk) {
            uint32_t ah[4];
#pragma unroll
            for (int t2 = 0; t2 < 2; ++t2) {
                const int nj = 2 * kk + t2;
                const float p0 = __expf(sacc[nj][0] - mn0);
                const float p1 = __expf(sacc[nj][1] - mn0);
                const float p2 = __expf(sacc[nj][2] - mn1);
                const float p3 = __expf(sacc[nj][3] - mn1);
                s0 += p0 + p1; s1 += p2 + p3;
                ah[2 * t2 + 0] = pack_h2(p0, p1);
                ah[2 * t2 + 1] = pack_h2(p2, p3);
            }
            uint32_t vh[4][4], vl[4][4];
#pragma unroll
            for (int n2 = 0; n2 < 4; ++n2) {
                const uint32_t off = (uint32_t)(n2 * 16 + lrow) * 128u
                                   + (((uint32_t)kk * 32u + lcol) ^ xr);
                ldsm_x4(vh[n2][0], vh[n2][1], vh[n2][2], vh[n2][3], st + 16384u + off);
                ldsm_x4(vl[n2][0], vl[n2][1], vl[n2][2], vl[n2][3], st + 24576u + off);
            }
#pragma unroll
            for (int nj = 0; nj < 8; ++nj) {
                const int n2 = nj >> 1, h = nj & 1;
                mma_f16(ctx[nj], ah, vh[n2][h], vh[n2][h + 2]);
                mma_f16(ctx[nj], ah, vl[n2][h], vl[n2][h + 2]);
            }
        }
        s0 += __shfl_xor_sync(0xffffffffu, s0, 1);
        s0 += __shfl_xor_sync(0xffffffffu, s0, 2);
        s1 += __shfl_xor_sync(0xffffffffu, s1, 1);
        s1 += __shfl_xor_sync(0xffffffffu, s1, 2);
        lr0 = lr0 * cc0 + s0;
        lr1 = lr1 * cc1 + s1;

        __syncthreads();
    }

    // ---- epilogue: normalize, write ctx as fp16 into A slot 0 ----
    const float i0 = 1.0f / lr0;
    const float i1 = 1.0f / lr1;
    const int b  = bh >> 4;
    const int hh = bh & 15;
    const int gq = lane >> 2;
    const int tq = lane & 3;
    const int r0 = q0 + wid * 16 + gq;
    const int r1 = r0 + 8;
#pragma unroll
    for (int nj = 0; nj < 8; ++nj) {
        const int col = hh * 64 + nj * 8 + tq * 2;
        {
            const size_t idx = ((size_t)r0 * BATCH + b) * DMODEL + col;
            *(__half2*)&g_Af[idx] =
                __floats2half2_rn(ctx[nj][0] * i0, ctx[nj][1] * i0);
        }
        {
            const size_t idx = ((size_t)r1 * BATCH + b) * DMODEL + col;
            *(__half2*)&g_Af[idx] =
                __floats2half2_rn(ctx[nj][2] * i1, ctx[nj][3] * i1);
        }
    }
}

// ---------------------------------------------------------------------------
// kernel_launch
// order: query, key, value, time_decay, Wq, bq, Wk, bk, Wv, bv, Wo, bo
// ---------------------------------------------------------------------------
extern "C" void kernel_launch(void* const* d_in, const int* in_sizes, int n_in,
                              void* d_out, int out_size)
{
    const float* query      = (const float*)d_in[0];
    const float* key        = (const float*)d_in[1];
    const float* value      = (const float*)d_in[2];
    const float* time_decay = (const float*)d_in[3];
    const float* Wq = (const float*)d_in[4];
    const float* bq = (const float*)d_in[5];
    const float* Wk = (const float*)d_in[6];
    const float* bk = (const float*)d_in[7];
    const float* Wv = (const float*)d_in[8];
    const float* bv = (const float*)d_in[9];
    const float* Wo = (const float*)d_in[10];
    const float* bo = (const float*)d_in[11];
    float* out = (float*)d_out;

    cudaFuncSetAttribute(gemm_all, cudaFuncAttributeMaxDynamicSharedMemorySize, GEMM_SMEM_BYTES);
    cudaFuncSetAttribute(attn_mma, cudaFuncAttributeMaxDynamicSharedMemorySize, ATTN_SMEM_BYTES);

    // 1. all conversions (two launches)
    conv_w_all<<<dim3(1024, 4), 256>>>(Wq, Wk, Wv, Wo);
    conv_a_all<<<dim3(8192, 3), 256>>>(query, key, value);

    // 2. fused QKV projections (one launch, grid.z = 3)
    gemm_all<<<dim3(8, 64, 3), 256, GEMM_SMEM_BYTES>>>(bq, bk, bv, nullptr, nullptr, -1);

    // 3. attention
    attn_mma<<<dim3(T_LEN / 64, NBH), 128, ATTN_SMEM_BYTES>>>();

    // 4. output projection (+ time_decay)
    gemm_all<<<dim3(8, 64, 1), 256, GEMM_SMEM_BYTES>>>(bo, nullptr, nullptr, out, time_decay, 3);
}

// round 16
// speedup vs baseline: 5.0526x; 1.0133x over previous
#include <cuda_runtime.h>
#include <cuda_bf16.h>
#include <cuda_fp16.h>
#include <math.h>
#include <stdint.h>

#define T_LEN  2048
#define BATCH  4
#define DMODEL 1024
#define NHEAD  16
#define HDIM   64
#define MROWS  (T_LEN * BATCH)   // 8192
#define NBH    (BATCH * NHEAD)   // 64
#define QKV_ELEMS ((size_t)NBH * T_LEN * HDIM)

// ---------------------------------------------------------------------------
// Scratch ( __device__ globals: no allocation allowed )
// ---------------------------------------------------------------------------
__device__ __half g_Qh[QKV_ELEMS];                  // [bh][t][hd], prescaled 1/8
__device__ __half g_Kh[QKV_ELEMS], g_Kl[QKV_ELEMS]; // [bh][t][hd], fp16 hi/lo
__device__ __half g_Vh[QKV_ELEMS], g_Vl[QKV_ELEMS]; // [bh][hd][t] (TRANSPOSED), fp16 hi/lo

// A slots 0..2 = q/k/v inputs (slot 0 reused by attn output for O-proj); fp16 single
__device__ __half g_Af[(size_t)3 * MROWS * DMODEL];
// W slots 0..3 = Wq, Wk, Wv, Wo; fp16 hi/lo split
__device__ __half g_Wh16[(size_t)4 * DMODEL * DMODEL];
__device__ __half g_Wl16[(size_t)4 * DMODEL * DMODEL];

// ---------------------------------------------------------------------------
// Primitives (compute_103-legal: mma.sync / ldmatrix / cp.async only)
// ---------------------------------------------------------------------------
__device__ __forceinline__ uint32_t smem_u32(const void* p) {
    uint32_t a;
    asm("{ .reg .u64 t; cvta.to.shared.u64 t, %1; cvt.u32.u64 %0, t; }"
        : "=r"(a) : "l"(p));
    return a;
}

__device__ __forceinline__ void ldsm_x4(uint32_t& r0, uint32_t& r1,
                                        uint32_t& r2, uint32_t& r3,
                                        uint32_t addr) {
    asm volatile("ldmatrix.sync.aligned.m8n8.x4.shared.b16 {%0,%1,%2,%3}, [%4];"
                 : "=r"(r0), "=r"(r1), "=r"(r2), "=r"(r3) : "r"(addr));
}

__device__ __forceinline__ void mma_f16(float* d, const uint32_t* a,
                                        uint32_t b0, uint32_t b1) {
    asm volatile(
        "mma.sync.aligned.m16n8k16.row.col.f32.f16.f16.f32 "
        "{%0,%1,%2,%3}, {%4,%5,%6,%7}, {%8,%9}, {%0,%1,%2,%3};"
        : "+f"(d[0]), "+f"(d[1]), "+f"(d[2]), "+f"(d[3])
        : "r"(a[0]), "r"(a[1]), "r"(a[2]), "r"(a[3]), "r"(b0), "r"(b1));
}

// pack two fp32 -> f16x2 register (lo element in low half)
__device__ __forceinline__ uint32_t pack_h2(float lo_e, float hi_e) {
    uint32_t r;
    asm("cvt.rn.f16x2.f32 %0, %1, %2;" : "=r"(r) : "f"(hi_e), "f"(lo_e));
    return r;
}

__device__ __forceinline__ void cp16(uint32_t dst, const void* src) {
    asm volatile("cp.async.cg.shared.global [%0], [%1], 16;"
                 :: "r"(dst), "l"((uint64_t)__cvta_generic_to_global(src)));
}
#define CP_COMMIT() asm volatile("cp.async.commit_group;")
#define CP_WAIT(n)  asm volatile("cp.async.wait_group %0;" :: "n"(n))

// ---------------------------------------------------------------------------
// Conversions: activations -> fp16 single; weights -> fp16 hi/lo
// ---------------------------------------------------------------------------
__global__ void __launch_bounds__(256)
conv_a_all(const float* __restrict__ q, const float* __restrict__ k,
           const float* __restrict__ v)
{
    const int slot = blockIdx.y;
    const float* src = (slot == 0) ? q : (slot == 1) ? k : v;
    const size_t i = ((size_t)blockIdx.x * 256 + threadIdx.x) * 4;
    const size_t o = (size_t)slot * MROWS * DMODEL + i;
    const float4 x = *(const float4*)(src + i);
    *(__half2*)(g_Af + o)     = __floats2half2_rn(x.x, x.y);
    *(__half2*)(g_Af + o + 2) = __floats2half2_rn(x.z, x.w);
}

__global__ void __launch_bounds__(256)
conv_w_all(const float* __restrict__ wq, const float* __restrict__ wk,
           const float* __restrict__ wv, const float* __restrict__ wo)
{
    const int slot = blockIdx.y;
    const float* src = (slot == 0) ? wq : (slot == 1) ? wk : (slot == 2) ? wv : wo;
    const size_t i = ((size_t)blockIdx.x * 256 + threadIdx.x) * 4;
    const size_t o = (size_t)slot * DMODEL * DMODEL + i;
    const float4 x = *(const float4*)(src + i);
    const __half h0 = __float2half_rn(x.x);
    const __half h1 = __float2half_rn(x.y);
    const __half h2 = __float2half_rn(x.z);
    const __half h3 = __float2half_rn(x.w);
    *(__half2*)(g_Wh16 + o)     = __halves2half2(h0, h1);
    *(__half2*)(g_Wh16 + o + 2) = __halves2half2(h2, h3);
    *(__half2*)(g_Wl16 + o) =
        __floats2half2_rn(x.x - __half2float(h0), x.y - __half2float(h1));
    *(__half2*)(g_Wl16 + o + 2) =
        __floats2half2_rn(x.z - __half2float(h2), x.w - __half2float(h3));
}

// ---------------------------------------------------------------------------
// fp16 one-sided GEMM: C = A_f16 @ (W_hi + W_lo)^T  (2 MMA passes)
//   mode 0: Q -> g_Qh [bh][t][hd] fp16, scaled 1/8
//   mode 1: K -> g_Kh/g_Kl [bh][t][hd] fp16 hi/lo
//   mode 2: V -> g_Vh/g_Vl [bh][hd][t] fp16 hi/lo (transposed scatter)
//   mode 3: out = (C + bias) * time_decay (A = slot 0, W = slot 3)
// smem: 2 stages x {A, Whi, Wlo tiles of 16KB} = 98304 B -> 2 CTAs/SM.
// ---------------------------------------------------------------------------
#define GEMM_SMEM_BYTES 98304

__device__ __forceinline__ void gemm_load_chunk(
    uint32_t sbase, uint32_t stage, int tid, int m0, int n0, int kt,
    const __half* aF, const __half* wHi, const __half* wLo)
{
#pragma unroll
    for (int t3 = 0; t3 < 3; ++t3) {
        const __half* src = (t3 == 0) ? aF : (t3 == 1) ? wHi : wLo;
        const int rbase = (t3 == 0) ? m0 : n0;
#pragma unroll
        for (int i = 0; i < 4; ++i) {
            const int s   = tid + i * 256;
            const int row = s >> 3;
            const int chk = s & 7;
            const uint32_t so = stage + (uint32_t)t3 * 16384u + (uint32_t)row * 128u
                              + (((uint32_t)chk * 16u) ^ (((uint32_t)row & 7u) << 4));
            cp16(sbase + so, src + (size_t)(rbase + row) * DMODEL + kt + chk * 8);
        }
    }
}

__global__ void __launch_bounds__(256, 2)
gemm_all(const float* __restrict__ b0, const float* __restrict__ b1,
         const float* __restrict__ b2, float* __restrict__ out,
         const float* __restrict__ td, int which)
{
    extern __shared__ __align__(128) char smem[];
    const uint32_t sbase = smem_u32(smem);

    const int mode = (which < 0) ? (int)blockIdx.z : which;
    const float* bias = (mode == 1) ? b1 : (mode == 2) ? b2 : b0;

    const size_t aoff = (mode < 3) ? (size_t)mode * MROWS * DMODEL : 0;
    const size_t woff = (size_t)mode * DMODEL * DMODEL;
    const __half* aF  = g_Af   + aoff;
    const __half* wHi = g_Wh16 + woff;
    const __half* wLo = g_Wl16 + woff;

    const int tid  = threadIdx.x;
    const int wid  = tid >> 5;
    const int lane = tid & 31;
    const int m0 = blockIdx.y * 128;
    const int n0 = blockIdx.x * 128;

    const int wm = (wid >> 1) * 32;
    const int wn = (wid & 1) * 64;

    const int sub = lane >> 3;
    const int r8  = lane & 7;
    const uint32_t xr = (uint32_t)r8 << 4;
    const int lrow_off = r8 + ((sub & 1) << 3);
    const uint32_t lcol_b = (uint32_t)((sub >> 1) << 4);

    float acc[2][8][4];
#pragma unroll
    for (int i = 0; i < 2; i++)
#pragma unroll
        for (int j = 0; j < 8; j++)
#pragma unroll
            for (int q = 0; q < 4; q++) acc[i][j][q] = 0.0f;

    gemm_load_chunk(sbase, 0, tid, m0, n0, 0, aF, wHi, wLo);
    CP_COMMIT();

    for (int kc = 0; kc < 16; ++kc) {
        if (kc < 15) {
            gemm_load_chunk(sbase, (uint32_t)((kc + 1) & 1) * 49152u, tid,
                            m0, n0, (kc + 1) * 64, aF, wHi, wLo);
            CP_COMMIT();
            CP_WAIT(1);
        } else {
            CP_WAIT(0);
        }
        __syncthreads();

        const uint32_t st = sbase + (uint32_t)(kc & 1) * 49152u;
#pragma unroll
        for (int ks = 0; ks < 4; ++ks) {
            const uint32_t kb = (uint32_t)ks * 32u + lcol_b;

            uint32_t aFr[2][4], wHiF[4][4], wLoF[4][4];
#pragma unroll
            for (int mi = 0; mi < 2; ++mi) {
                const uint32_t row = (uint32_t)(wm + mi * 16 + lrow_off);
                const uint32_t off = row * 128u + (kb ^ xr);
                ldsm_x4(aFr[mi][0], aFr[mi][1], aFr[mi][2], aFr[mi][3], st + off);
            }
#pragma unroll
            for (int nj2 = 0; nj2 < 4; ++nj2) {
                const uint32_t row = (uint32_t)(wn + nj2 * 16 + lrow_off);
                const uint32_t off = row * 128u + (kb ^ xr);
                ldsm_x4(wHiF[nj2][0], wHiF[nj2][1], wHiF[nj2][2], wHiF[nj2][3], st + 16384u + off);
                ldsm_x4(wLoF[nj2][0], wLoF[nj2][1], wLoF[nj2][2], wLoF[nj2][3], st + 32768u + off);
            }
#pragma unroll
            for (int mi = 0; mi < 2; ++mi)
#pragma unroll
                for (int nj = 0; nj < 8; ++nj) {
                    const int n2 = nj >> 1;
                    const int hi = nj & 1;
                    mma_f16(acc[mi][nj], aFr[mi], wHiF[n2][hi], wHiF[n2][hi + 2]);
                    mma_f16(acc[mi][nj], aFr[mi], wLoF[n2][hi], wLoF[n2][hi + 2]);
                }
        }
        __syncthreads();
    }

    // ---- epilogue ----
    const int gq = lane >> 2;
    const int tq = lane & 3;
#pragma unroll
    for (int mi = 0; mi < 2; ++mi) {
#pragma unroll
        for (int half = 0; half < 2; ++half) {
            const int m = m0 + wm + mi * 16 + gq + half * 8;
#pragma unroll
            for (int nj = 0; nj < 8; ++nj) {
                const int col = n0 + wn + nj * 8 + tq * 2;
                float v0 = acc[mi][nj][half * 2 + 0] + bias[col];
                float v1 = acc[mi][nj][half * 2 + 1] + bias[col + 1];
                if (mode == 3) {
                    const size_t idx = (size_t)m * DMODEL + col;
                    const float2 tv = *(const float2*)&td[idx];
                    *(float2*)&out[idx] = make_float2(v0 * tv.x, v1 * tv.y);
                } else {
                    const int trow = m >> 2;
                    const int b    = m & 3;
                    const int hh   = col >> 6;
                    const int hd   = col & 63;
                    if (mode == 0) {
                        const size_t base = ((size_t)(b * NHEAD + hh) * T_LEN + trow) * HDIM + hd;
                        *(__half2*)&g_Qh[base] = __floats2half2_rn(v0 * 0.125f, v1 * 0.125f);
                    } else if (mode == 1) {
                        const size_t base = ((size_t)(b * NHEAD + hh) * T_LEN + trow) * HDIM + hd;
                        const __half h0 = __float2half_rn(v0);
                        const __half h1 = __float2half_rn(v1);
                        *(__half2*)&g_Kh[base] = __halves2half2(h0, h1);
                        *(__half2*)&g_Kl[base] =
                            __floats2half2_rn(v0 - __half2float(h0), v1 - __half2float(h1));
                    } else {
                        const size_t base = ((size_t)(b * NHEAD + hh) * HDIM + hd) * T_LEN + trow;
                        const __half h0 = __float2half_rn(v0);
                        const __half h1 = __float2half_rn(v1);
                        g_Vh[base]         = h0;
                        g_Vh[base + T_LEN] = h1;
                        g_Vl[base]         = __float2half_rn(v0 - __half2float(h0));
                        g_Vl[base + T_LEN] = __float2half_rn(v1 - __half2float(h1));
                    }
                }
            }
        }
    }
}

// ---------------------------------------------------------------------------
// Flash attention, fp16 one-sided-corrected, 128 q-rows / 8 warps per CTA:
//   S = Q_f16 · (K_hi + K_lo)   (2 passes)
//   O = P_f16 · (V_hi + V_lo)   (2 passes)
// B-fragment (K/V) ldmatrix traffic per CTA is unchanged while queries per
// CTA double -> per-query L1 traffic halves vs the 64-row version.
// smem: 2 stages x 32KB {Kh,Kl,Vh,Vl @ +0/+8K/+16K/+24K};
// Q (128 rows, 16KB) staged through stage 1 before the loop.
// Output -> fp16 into g_Af slot 0 (O-proj A operand).
// ---------------------------------------------------------------------------
#define ATTN_SMEM_BYTES 65536

__device__ __forceinline__ void attn_load_chunk(
    uint32_t sbase, uint32_t stage, int tid, int kt,
    size_t baseRM, size_t baseVT)
{
#pragma unroll
    for (int i = 0; i < 2; ++i) {
        const int s = tid + i * 256;          // 0..511 16B slots (64 rows x 8)
        const int row = s >> 3, c16 = s & 7;
        const uint32_t so = stage + (uint32_t)row * 128u
            + (((uint32_t)c16 * 16u) ^ (((uint32_t)row & 7u) << 4));
        const size_t gk = baseRM + (size_t)(kt + row) * HDIM + c16 * 8;
        const size_t gv = baseVT + (size_t)row * T_LEN + kt + c16 * 8;
        cp16(sbase + so,          g_Kh + gk);
        cp16(sbase + 8192u + so,  g_Kl + gk);
        cp16(sbase + 16384u + so, g_Vh + gv);
        cp16(sbase + 24576u + so, g_Vl + gv);
    }
}

__global__ void __launch_bounds__(256, 2)
attn_mma()
{
    extern __shared__ __align__(1024) char sm[];
    const uint32_t sb = smem_u32(sm);

    const int tid  = threadIdx.x;
    const int wid  = tid >> 5;                // 0..7
    const int lane = tid & 31;
    const int bh   = blockIdx.y;
    const int q0   = blockIdx.x * 128;
    const size_t baseRM = (size_t)bh * T_LEN * HDIM;
    const size_t baseVT = (size_t)bh * HDIM * T_LEN;

    const int sub = lane >> 3;
    const int r8  = lane & 7;
    const uint32_t xr = (uint32_t)r8 << 4;
    const int lrow = r8 + ((sub & 1) << 3);
    const uint32_t lcol = (uint32_t)((sub >> 1) << 4);

    // ---- prologue: chunk0 -> stage0; Q (128 rows) -> stage1 area ----
    attn_load_chunk(sb, 0, tid, 0, baseRM, baseVT);
    CP_COMMIT();
#pragma unroll
    for (int i = 0; i < 4; ++i) {
        const int s = tid + i * 256;          // 0..1023 slots (128 rows x 8)
        const int row = s >> 3, c16 = s & 7;
        const uint32_t so = (uint32_t)row * 128u
            + (((uint32_t)c16 * 16u) ^ (((uint32_t)row & 7u) << 4));
        cp16(sb + 32768u + so, g_Qh + baseRM + (size_t)(q0 + row) * HDIM + c16 * 8);
    }
    CP_COMMIT();
    CP_WAIT(0);
    __syncthreads();

    uint32_t qh[4][4];
    {
        const uint32_t qrow = (uint32_t)(wid * 16 + lrow);
#pragma unroll
        for (int ks = 0; ks < 4; ++ks) {
            const uint32_t off = qrow * 128u + (((uint32_t)ks * 32u + lcol) ^ xr);
            ldsm_x4(qh[ks][0], qh[ks][1], qh[ks][2], qh[ks][3], sb + 32768u + off);
        }
    }
    __syncthreads();   // stage1 free for chunk1

    float ctx[8][4];
#pragma unroll
    for (int j = 0; j < 8; ++j)
#pragma unroll
        for (int q = 0; q < 4; ++q) ctx[j][q] = 0.0f;
    float mr0 = -1e30f, mr1 = -1e30f, lr0 = 0.0f, lr1 = 0.0f;

    for (int c = 0; c < T_LEN / 64; ++c) {
        if (c < T_LEN / 64 - 1) {
            attn_load_chunk(sb, (uint32_t)((c + 1) & 1) * 32768u, tid,
                            (c + 1) * 64, baseRM, baseVT);
            CP_COMMIT();
            CP_WAIT(1);
        } else {
            CP_WAIT(0);
        }
        __syncthreads();

        const uint32_t st = sb + (uint32_t)(c & 1) * 32768u;

        // ---- S = Q (Khi + Klo) ----
        float sacc[8][4];
#pragma unroll
        for (int j = 0; j < 8; ++j)
#pragma unroll
            for (int q = 0; q < 4; ++q) sacc[j][q] = 0.0f;

#pragma unroll
        for (int ks = 0; ks < 4; ++ks) {
            uint32_t kh[4][4], kl[4][4];
#pragma unroll
            for (int n2 = 0; n2 < 4; ++n2) {
                const uint32_t off = (uint32_t)(n2 * 16 + lrow) * 128u
                                   + (((uint32_t)ks * 32u + lcol) ^ xr);
                ldsm_x4(kh[n2][0], kh[n2][1], kh[n2][2], kh[n2][3], st + off);
                ldsm_x4(kl[n2][0], kl[n2][1], kl[n2][2], kl[n2][3], st + 8192u + off);
            }
#pragma unroll
            for (int nj = 0; nj < 8; ++nj) {
                const int n2 = nj >> 1, h = nj & 1;
                mma_f16(sacc[nj], qh[ks], kh[n2][h], kh[n2][h + 2]);
                mma_f16(sacc[nj], qh[ks], kl[n2][h], kl[n2][h + 2]);
            }
        }

        // ---- online softmax ----
        float mt0 = -1e30f, mt1 = -1e30f;
#pragma unroll
        for (int nj = 0; nj < 8; ++nj) {
            mt0 = fmaxf(mt0, fmaxf(sacc[nj][0], sacc[nj][1]));
            mt1 = fmaxf(mt1, fmaxf(sacc[nj][2], sacc[nj][3]));
        }
        mt0 = fmaxf(mt0, __shfl_xor_sync(0xffffffffu, mt0, 1));
        mt0 = fmaxf(mt0, __shfl_xor_sync(0xffffffffu, mt0, 2));
        mt1 = fmaxf(mt1, __shfl_xor_sync(0xffffffffu, mt1, 1));
        mt1 = fmaxf(mt1, __shfl_xor_sync(0xffffffffu, mt1, 2));
        const float mn0 = fmaxf(mr0, mt0);
        const float mn1 = fmaxf(mr1, mt1);
        const float cc0 = __expf(mr0 - mn0);
        const float cc1 = __expf(mr1 - mn1);
        mr0 = mn0; mr1 = mn1;
#pragma unroll
        for (int nj = 0; nj < 8; ++nj) {
            ctx[nj][0] *= cc0; ctx[nj][1] *= cc0;
            ctx[nj][2] *= cc1; ctx[nj][3] *= cc1;
        }

        // ---- P = exp(S - m) (fp16) + P (Vhi + Vlo) ----
        float s0 = 0.0f, s1 = 0.0f;
#pragma unroll
        for (int kk = 0; kk < 4; ++kk) {
            uint32_t ah[4];
#pragma unroll
            for (int t2 = 0; t2 < 2; ++t2) {
                const int nj = 2 * kk + t2;
                const float p0 = __expf(sacc[nj][0] - mn0);
                const float p1 = __expf(sacc[nj][1] - mn0);
                const float p2 = __expf(sacc[nj][2] - mn1);
                const float p3 = __expf(sacc[nj][3] - mn1);
                s0 += p0 + p1; s1 += p2 + p3;
                ah[2 * t2 + 0] = pack_h2(p0, p1);
                ah[2 * t2 + 1] = pack_h2(p2, p3);
            }
            uint32_t vh[4][4], vl[4][4];
#pragma unroll
            for (int n2 = 0; n2 < 4; ++n2) {
                const uint32_t off = (uint32_t)(n2 * 16 + lrow) * 128u
                                   + (((uint32_t)kk * 32u + lcol) ^ xr);
                ldsm_x4(vh[n2][0], vh[n2][1], vh[n2][2], vh[n2][3], st + 16384u + off);
                ldsm_x4(vl[n2][0], vl[n2][1], vl[n2][2], vl[n2][3], st + 24576u + off);
            }
#pragma unroll
            for (int nj = 0; nj < 8; ++nj) {
                const int n2 = nj >> 1, h = nj & 1;
                mma_f16(ctx[nj], ah, vh[n2][h], vh[n2][h + 2]);
                mma_f16(ctx[nj], ah, vl[n2][h], vl[n2][h + 2]);
            }
        }
        s0 += __shfl_xor_sync(0xffffffffu, s0, 1);
        s0 += __shfl_xor_sync(0xffffffffu, s0, 2);
        s1 += __shfl_xor_sync(0xffffffffu, s1, 1);
        s1 += __shfl_xor_sync(0xffffffffu, s1, 2);
        lr0 = lr0 * cc0 + s0;
        lr1 = lr1 * cc1 + s1;

        __syncthreads();
    }

    // ---- epilogue: normalize, write ctx as fp16 into A slot 0 ----
    const float i0 = 1.0f / lr0;
    const float i1 = 1.0f / lr1;
    const int b  = bh >> 4;
    const int hh = bh & 15;
    const int gq = lane >> 2;
    const int tq = lane & 3;
    const int r0 = q0 + wid * 16 + gq;
    const int r1 = r0 + 8;
#pragma unroll
    for (int nj = 0; nj < 8; ++nj) {
        const int col = hh * 64 + nj * 8 + tq * 2;
        {
            const size_t idx = ((size_t)r0 * BATCH + b) * DMODEL + col;
            *(__half2*)&g_Af[idx] =
                __floats2half2_rn(ctx[nj][0] * i0, ctx[nj][1] * i0);
        }
        {
            const size_t idx = ((size_t)r1 * BATCH + b) * DMODEL + col;
            *(__half2*)&g_Af[idx] =
                __floats2half2_rn(ctx[nj][2] * i1, ctx[nj][3] * i1);
        }
    }
}

// ---------------------------------------------------------------------------
// kernel_launch
// order: query, key, value, time_decay, Wq, bq, Wk, bk, Wv, bv, Wo, bo
// ---------------------------------------------------------------------------
extern "C" void kernel_launch(void* const* d_in, const int* in_sizes, int n_in,
                              void* d_out, int out_size)
{
    const float* query      = (const float*)d_in[0];
    const float* key        = (const float*)d_in[1];
    const float* value      = (const float*)d_in[2];
    const float* time_decay = (const float*)d_in[3];
    const float* Wq = (const float*)d_in[4];
    const float* bq = (const float*)d_in[5];
    const float* Wk = (const float*)d_in[6];
    const float* bk = (const float*)d_in[7];
    const float* Wv = (const float*)d_in[8];
    const float* bv = (const float*)d_in[9];
    const float* Wo = (const float*)d_in[10];
    const float* bo = (const float*)d_in[11];
    float* out = (float*)d_out;

    cudaFuncSetAttribute(gemm_all, cudaFuncAttributeMaxDynamicSharedMemorySize, GEMM_SMEM_BYTES);
    cudaFuncSetAttribute(attn_mma, cudaFuncAttributeMaxDynamicSharedMemorySize, ATTN_SMEM_BYTES);

    // 1. all conversions (two launches)
    conv_w_all<<<dim3(1024, 4), 256>>>(Wq, Wk, Wv, Wo);
    conv_a_all<<<dim3(8192, 3), 256>>>(query, key, value);

    // 2. fused QKV projections (one launch, grid.z = 3)
    gemm_all<<<dim3(8, 64, 3), 256, GEMM_SMEM_BYTES>>>(bq, bk, bv, nullptr, nullptr, -1);

    // 3. attention (128 q-rows per CTA)
    attn_mma<<<dim3(T_LEN / 128, NBH), 256, ATTN_SMEM_BYTES>>>();

    // 4. output projection (+ time_decay)
    gemm_all<<<dim3(8, 64, 1), 256, GEMM_SMEM_BYTES>>>(bo, nullptr, nullptr, out, time_decay, 3);
}

// round 17
// speedup vs baseline: 5.2777x; 1.0446x over previous
#include <cuda_runtime.h>
#include <cuda_bf16.h>
#include <cuda_fp16.h>
#include <math.h>
#include <stdint.h>

#define T_LEN  2048
#define BATCH  4
#define DMODEL 1024
#define NHEAD  16
#define HDIM   64
#define MROWS  (T_LEN * BATCH)   // 8192
#define NBH    (BATCH * NHEAD)   // 64
#define QKV_ELEMS ((size_t)NBH * T_LEN * HDIM)

// ---------------------------------------------------------------------------
// Scratch ( __device__ globals: no allocation allowed )
// ---------------------------------------------------------------------------
__device__ __half g_Qh[QKV_ELEMS];                  // [bh][t][hd], prescaled 1/8
__device__ __half g_Kh[QKV_ELEMS], g_Kl[QKV_ELEMS]; // [bh][t][hd], fp16 hi/lo
__device__ __half g_Vh[QKV_ELEMS], g_Vl[QKV_ELEMS]; // [bh][hd][t] (TRANSPOSED), fp16 hi/lo

// A slots 0..2 = q/k/v inputs (slot 0 reused by attn output for O-proj); fp16 single
__device__ __half g_Af[(size_t)3 * MROWS * DMODEL];
// W slots 0..3 = Wq, Wk, Wv, Wo; fp16 hi/lo split
__device__ __half g_Wh16[(size_t)4 * DMODEL * DMODEL];
__device__ __half g_Wl16[(size_t)4 * DMODEL * DMODEL];

// ---------------------------------------------------------------------------
// Primitives (compute_103-legal: mma.sync / ldmatrix / cp.async only)
// ---------------------------------------------------------------------------
__device__ __forceinline__ uint32_t smem_u32(const void* p) {
    uint32_t a;
    asm("{ .reg .u64 t; cvta.to.shared.u64 t, %1; cvt.u32.u64 %0, t; }"
        : "=r"(a) : "l"(p));
    return a;
}

__device__ __forceinline__ void ldsm_x4(uint32_t& r0, uint32_t& r1,
                                        uint32_t& r2, uint32_t& r3,
                                        uint32_t addr) {
    asm volatile("ldmatrix.sync.aligned.m8n8.x4.shared.b16 {%0,%1,%2,%3}, [%4];"
                 : "=r"(r0), "=r"(r1), "=r"(r2), "=r"(r3) : "r"(addr));
}

__device__ __forceinline__ void mma_f16(float* d, const uint32_t* a,
                                        uint32_t b0, uint32_t b1) {
    asm volatile(
        "mma.sync.aligned.m16n8k16.row.col.f32.f16.f16.f32 "
        "{%0,%1,%2,%3}, {%4,%5,%6,%7}, {%8,%9}, {%0,%1,%2,%3};"
        : "+f"(d[0]), "+f"(d[1]), "+f"(d[2]), "+f"(d[3])
        : "r"(a[0]), "r"(a[1]), "r"(a[2]), "r"(a[3]), "r"(b0), "r"(b1));
}

// pack two fp32 -> f16x2 register (lo element in low half)
__device__ __forceinline__ uint32_t pack_h2(float lo_e, float hi_e) {
    uint32_t r;
    asm("cvt.rn.f16x2.f32 %0, %1, %2;" : "=r"(r) : "f"(hi_e), "f"(lo_e));
    return r;
}

__device__ __forceinline__ void cp16(uint32_t dst, const void* src) {
    asm volatile("cp.async.cg.shared.global [%0], [%1], 16;"
                 :: "r"(dst), "l"((uint64_t)__cvta_generic_to_global(src)));
}
#define CP_COMMIT() asm volatile("cp.async.commit_group;")
#define CP_WAIT(n)  asm volatile("cp.async.wait_group %0;" :: "n"(n))

// ---------------------------------------------------------------------------
// Conversions: activations -> fp16 single; weights -> fp16 hi/lo
// ---------------------------------------------------------------------------
__global__ void __launch_bounds__(256)
conv_a_all(const float* __restrict__ q, const float* __restrict__ k,
           const float* __restrict__ v)
{
    const int slot = blockIdx.y;
    const float* src = (slot == 0) ? q : (slot == 1) ? k : v;
    const size_t i = ((size_t)blockIdx.x * 256 + threadIdx.x) * 4;
    const size_t o = (size_t)slot * MROWS * DMODEL + i;
    const float4 x = *(const float4*)(src + i);
    *(__half2*)(g_Af + o)     = __floats2half2_rn(x.x, x.y);
    *(__half2*)(g_Af + o + 2) = __floats2half2_rn(x.z, x.w);
}

__global__ void __launch_bounds__(256)
conv_w_all(const float* __restrict__ wq, const float* __restrict__ wk,
           const float* __restrict__ wv, const float* __restrict__ wo)
{
    const int slot = blockIdx.y;
    const float* src = (slot == 0) ? wq : (slot == 1) ? wk : (slot == 2) ? wv : wo;
    const size_t i = ((size_t)blockIdx.x * 256 + threadIdx.x) * 4;
    const size_t o = (size_t)slot * DMODEL * DMODEL + i;
    const float4 x = *(const float4*)(src + i);
    const __half h0 = __float2half_rn(x.x);
    const __half h1 = __float2half_rn(x.y);
    const __half h2 = __float2half_rn(x.z);
    const __half h3 = __float2half_rn(x.w);
    *(__half2*)(g_Wh16 + o)     = __halves2half2(h0, h1);
    *(__half2*)(g_Wh16 + o + 2) = __halves2half2(h2, h3);
    *(__half2*)(g_Wl16 + o) =
        __floats2half2_rn(x.x - __half2float(h0), x.y - __half2float(h1));
    *(__half2*)(g_Wl16 + o + 2) =
        __floats2half2_rn(x.z - __half2float(h2), x.w - __half2float(h3));
}

// ---------------------------------------------------------------------------
// fp16 one-sided GEMM (unchanged from R14): C = A_f16 @ (W_hi + W_lo)^T
// ---------------------------------------------------------------------------
#define GEMM_SMEM_BYTES 98304

__device__ __forceinline__ void gemm_load_chunk(
    uint32_t sbase, uint32_t stage, int tid, int m0, int n0, int kt,
    const __half* aF, const __half* wHi, const __half* wLo)
{
#pragma unroll
    for (int t3 = 0; t3 < 3; ++t3) {
        const __half* src = (t3 == 0) ? aF : (t3 == 1) ? wHi : wLo;
        const int rbase = (t3 == 0) ? m0 : n0;
#pragma unroll
        for (int i = 0; i < 4; ++i) {
            const int s   = tid + i * 256;
            const int row = s >> 3;
            const int chk = s & 7;
            const uint32_t so = stage + (uint32_t)t3 * 16384u + (uint32_t)row * 128u
                              + (((uint32_t)chk * 16u) ^ (((uint32_t)row & 7u) << 4));
            cp16(sbase + so, src + (size_t)(rbase + row) * DMODEL + kt + chk * 8);
        }
    }
}

__global__ void __launch_bounds__(256, 2)
gemm_all(const float* __restrict__ b0, const float* __restrict__ b1,
         const float* __restrict__ b2, float* __restrict__ out,
         const float* __restrict__ td, int which)
{
    extern __shared__ __align__(128) char smem[];
    const uint32_t sbase = smem_u32(smem);

    const int mode = (which < 0) ? (int)blockIdx.z : which;
    const float* bias = (mode == 1) ? b1 : (mode == 2) ? b2 : b0;

    const size_t aoff = (mode < 3) ? (size_t)mode * MROWS * DMODEL : 0;
    const size_t woff = (size_t)mode * DMODEL * DMODEL;
    const __half* aF  = g_Af   + aoff;
    const __half* wHi = g_Wh16 + woff;
    const __half* wLo = g_Wl16 + woff;

    const int tid  = threadIdx.x;
    const int wid  = tid >> 5;
    const int lane = tid & 31;
    const int m0 = blockIdx.y * 128;
    const int n0 = blockIdx.x * 128;

    const int wm = (wid >> 1) * 32;
    const int wn = (wid & 1) * 64;

    const int sub = lane >> 3;
    const int r8  = lane & 7;
    const uint32_t xr = (uint32_t)r8 << 4;
    const int lrow_off = r8 + ((sub & 1) << 3);
    const uint32_t lcol_b = (uint32_t)((sub >> 1) << 4);

    float acc[2][8][4];
#pragma unroll
    for (int i = 0; i < 2; i++)
#pragma unroll
        for (int j = 0; j < 8; j++)
#pragma unroll
            for (int q = 0; q < 4; q++) acc[i][j][q] = 0.0f;

    gemm_load_chunk(sbase, 0, tid, m0, n0, 0, aF, wHi, wLo);
    CP_COMMIT();

    for (int kc = 0; kc < 16; ++kc) {
        if (kc < 15) {
            gemm_load_chunk(sbase, (uint32_t)((kc + 1) & 1) * 49152u, tid,
                            m0, n0, (kc + 1) * 64, aF, wHi, wLo);
            CP_COMMIT();
            CP_WAIT(1);
        } else {
            CP_WAIT(0);
        }
        __syncthreads();

        const uint32_t st = sbase + (uint32_t)(kc & 1) * 49152u;
#pragma unroll
        for (int ks = 0; ks < 4; ++ks) {
            const uint32_t kb = (uint32_t)ks * 32u + lcol_b;

            uint32_t aFr[2][4], wHiF[4][4], wLoF[4][4];
#pragma unroll
            for (int mi = 0; mi < 2; ++mi) {
                const uint32_t row = (uint32_t)(wm + mi * 16 + lrow_off);
                const uint32_t off = row * 128u + (kb ^ xr);
                ldsm_x4(aFr[mi][0], aFr[mi][1], aFr[mi][2], aFr[mi][3], st + off);
            }
#pragma unroll
            for (int nj2 = 0; nj2 < 4; ++nj2) {
                const uint32_t row = (uint32_t)(wn + nj2 * 16 + lrow_off);
                const uint32_t off = row * 128u + (kb ^ xr);
                ldsm_x4(wHiF[nj2][0], wHiF[nj2][1], wHiF[nj2][2], wHiF[nj2][3], st + 16384u + off);
                ldsm_x4(wLoF[nj2][0], wLoF[nj2][1], wLoF[nj2][2], wLoF[nj2][3], st + 32768u + off);
            }
#pragma unroll
            for (int mi = 0; mi < 2; ++mi)
#pragma unroll
                for (int nj = 0; nj < 8; ++nj) {
                    const int n2 = nj >> 1;
                    const int hi = nj & 1;
                    mma_f16(acc[mi][nj], aFr[mi], wHiF[n2][hi], wHiF[n2][hi + 2]);
                    mma_f16(acc[mi][nj], aFr[mi], wLoF[n2][hi], wLoF[n2][hi + 2]);
                }
        }
        __syncthreads();
    }

    // ---- epilogue ----
    const int gq = lane >> 2;
    const int tq = lane & 3;
#pragma unroll
    for (int mi = 0; mi < 2; ++mi) {
#pragma unroll
        for (int half = 0; half < 2; ++half) {
            const int m = m0 + wm + mi * 16 + gq + half * 8;
#pragma unroll
            for (int nj = 0; nj < 8; ++nj) {
                const int col = n0 + wn + nj * 8 + tq * 2;
                float v0 = acc[mi][nj][half * 2 + 0] + bias[col];
                float v1 = acc[mi][nj][half * 2 + 1] + bias[col + 1];
                if (mode == 3) {
                    const size_t idx = (size_t)m * DMODEL + col;
                    const float2 tv = *(const float2*)&td[idx];
                    *(float2*)&out[idx] = make_float2(v0 * tv.x, v1 * tv.y);
                } else {
                    const int trow = m >> 2;
                    const int b    = m & 3;
                    const int hh   = col >> 6;
                    const int hd   = col & 63;
                    if (mode == 0) {
                        const size_t base = ((size_t)(b * NHEAD + hh) * T_LEN + trow) * HDIM + hd;
                        *(__half2*)&g_Qh[base] = __floats2half2_rn(v0 * 0.125f, v1 * 0.125f);
                    } else if (mode == 1) {
                        const size_t base = ((size_t)(b * NHEAD + hh) * T_LEN + trow) * HDIM + hd;
                        const __half h0 = __float2half_rn(v0);
                        const __half h1 = __float2half_rn(v1);
                        *(__half2*)&g_Kh[base] = __halves2half2(h0, h1);
                        *(__half2*)&g_Kl[base] =
                            __floats2half2_rn(v0 - __half2float(h0), v1 - __half2float(h1));
                    } else {
                        const size_t base = ((size_t)(b * NHEAD + hh) * HDIM + hd) * T_LEN + trow;
                        const __half h0 = __float2half_rn(v0);
                        const __half h1 = __float2half_rn(v1);
                        g_Vh[base]         = h0;
                        g_Vh[base + T_LEN] = h1;
                        g_Vl[base]         = __float2half_rn(v0 - __half2float(h0));
                        g_Vl[base + T_LEN] = __float2half_rn(v1 - __half2float(h1));
                    }
                }
            }
        }
    }
}

// ---------------------------------------------------------------------------
// Flash attention: 4 warps x 32 q-rows (2 M-tiles per warp) = 128 q-rows/CTA.
// Each K/V fragment load now feeds MMAs for TWO 16-row tiles -> ldsm bytes
// per MMA halve; per-chunk smem (~1024 cyc) < MMA (~1130 cyc) -> MMA-bound.
//   S = Q_f16 · (K_hi + K_lo), O = P_f16 · (V_hi + V_lo)
// smem: 2 stages x 32KB {Kh,Kl,Vh,Vl}; Q (128 rows) staged through stage 1.
// ---------------------------------------------------------------------------
#define ATTN_SMEM_BYTES 65536

__device__ __forceinline__ void attn_load_chunk(
    uint32_t sbase, uint32_t stage, int tid, int kt,
    size_t baseRM, size_t baseVT)
{
#pragma unroll
    for (int i = 0; i < 4; ++i) {
        const int s = tid + i * 128;          // 0..511 16B slots (64 rows x 8)
        const int row = s >> 3, c16 = s & 7;
        const uint32_t so = stage + (uint32_t)row * 128u
            + (((uint32_t)c16 * 16u) ^ (((uint32_t)row & 7u) << 4));
        const size_t gk = baseRM + (size_t)(kt + row) * HDIM + c16 * 8;
        const size_t gv = baseVT + (size_t)row * T_LEN + kt + c16 * 8;
        cp16(sbase + so,          g_Kh + gk);
        cp16(sbase + 8192u + so,  g_Kl + gk);
        cp16(sbase + 16384u + so, g_Vh + gv);
        cp16(sbase + 24576u + so, g_Vl + gv);
    }
}

__global__ void __launch_bounds__(128, 2)
attn_mma()
{
    extern __shared__ __align__(1024) char sm[];
    const uint32_t sb = smem_u32(sm);

    const int tid  = threadIdx.x;
    const int wid  = tid >> 5;                // 0..3
    const int lane = tid & 31;
    const int bh   = blockIdx.y;
    const int q0   = blockIdx.x * 128;
    const size_t baseRM = (size_t)bh * T_LEN * HDIM;
    const size_t baseVT = (size_t)bh * HDIM * T_LEN;

    const int sub = lane >> 3;
    const int r8  = lane & 7;
    const uint32_t xr = (uint32_t)r8 << 4;
    const int lrow = r8 + ((sub & 1) << 3);
    const uint32_t lcol = (uint32_t)((sub >> 1) << 4);

    // ---- prologue: chunk0 -> stage0; Q (128 rows) -> stage1 area ----
    attn_load_chunk(sb, 0, tid, 0, baseRM, baseVT);
    CP_COMMIT();
#pragma unroll
    for (int i = 0; i < 8; ++i) {
        const int s = tid + i * 128;          // 0..1023 slots (128 rows x 8)
        const int row = s >> 3, c16 = s & 7;
        const uint32_t so = (uint32_t)row * 128u
            + (((uint32_t)c16 * 16u) ^ (((uint32_t)row & 7u) << 4));
        cp16(sb + 32768u + so, g_Qh + baseRM + (size_t)(q0 + row) * HDIM + c16 * 8);
    }
    CP_COMMIT();
    CP_WAIT(0);
    __syncthreads();

    uint32_t qh[2][4][4];                     // [m-tile][ks][frag]
#pragma unroll
    for (int mi = 0; mi < 2; ++mi) {
        const uint32_t qrow = (uint32_t)(wid * 32 + mi * 16 + lrow);
#pragma unroll
        for (int ks = 0; ks < 4; ++ks) {
            const uint32_t off = qrow * 128u + (((uint32_t)ks * 32u + lcol) ^ xr);
            ldsm_x4(qh[mi][ks][0], qh[mi][ks][1], qh[mi][ks][2], qh[mi][ks][3],
                    sb + 32768u + off);
        }
    }
    __syncthreads();   // stage1 free for chunk1

    float ctx[2][8][4];
#pragma unroll
    for (int mi = 0; mi < 2; ++mi)
#pragma unroll
        for (int j = 0; j < 8; ++j)
#pragma unroll
            for (int q = 0; q < 4; ++q) ctx[mi][j][q] = 0.0f;
    float mr[2][2] = {{-1e30f, -1e30f}, {-1e30f, -1e30f}};
    float lr[2][2] = {{0.0f, 0.0f}, {0.0f, 0.0f}};

    for (int c = 0; c < T_LEN / 64; ++c) {
        if (c < T_LEN / 64 - 1) {
            attn_load_chunk(sb, (uint32_t)((c + 1) & 1) * 32768u, tid,
                            (c + 1) * 64, baseRM, baseVT);
            CP_COMMIT();
            CP_WAIT(1);
        } else {
            CP_WAIT(0);
        }
        __syncthreads();

        const uint32_t st = sb + (uint32_t)(c & 1) * 32768u;

        // ---- S = Q (Khi + Klo), both m-tiles share K fragments ----
        float sacc[2][8][4];
#pragma unroll
        for (int mi = 0; mi < 2; ++mi)
#pragma unroll
            for (int j = 0; j < 8; ++j)
#pragma unroll
                for (int q = 0; q < 4; ++q) sacc[mi][j][q] = 0.0f;

#pragma unroll
        for (int ks = 0; ks < 4; ++ks) {
            uint32_t kh[4][4], kl[4][4];
#pragma unroll
            for (int n2 = 0; n2 < 4; ++n2) {
                const uint32_t off = (uint32_t)(n2 * 16 + lrow) * 128u
                                   + (((uint32_t)ks * 32u + lcol) ^ xr);
                ldsm_x4(kh[n2][0], kh[n2][1], kh[n2][2], kh[n2][3], st + off);
                ldsm_x4(kl[n2][0], kl[n2][1], kl[n2][2], kl[n2][3], st + 8192u + off);
            }
#pragma unroll
            for (int mi = 0; mi < 2; ++mi)
#pragma unroll
                for (int nj = 0; nj < 8; ++nj) {
                    const int n2 = nj >> 1, h = nj & 1;
                    mma_f16(sacc[mi][nj], qh[mi][ks], kh[n2][h], kh[n2][h + 2]);
                    mma_f16(sacc[mi][nj], qh[mi][ks], kl[n2][h], kl[n2][h + 2]);
                }
        }

        // ---- online softmax (per m-tile) ----
        float mn[2][2], cc[2][2];
#pragma unroll
        for (int mi = 0; mi < 2; ++mi) {
            float mt0 = -1e30f, mt1 = -1e30f;
#pragma unroll
            for (int nj = 0; nj < 8; ++nj) {
                mt0 = fmaxf(mt0, fmaxf(sacc[mi][nj][0], sacc[mi][nj][1]));
                mt1 = fmaxf(mt1, fmaxf(sacc[mi][nj][2], sacc[mi][nj][3]));
            }
            mt0 = fmaxf(mt0, __shfl_xor_sync(0xffffffffu, mt0, 1));
            mt0 = fmaxf(mt0, __shfl_xor_sync(0xffffffffu, mt0, 2));
            mt1 = fmaxf(mt1, __shfl_xor_sync(0xffffffffu, mt1, 1));
            mt1 = fmaxf(mt1, __shfl_xor_sync(0xffffffffu, mt1, 2));
            mn[mi][0] = fmaxf(mr[mi][0], mt0);
            mn[mi][1] = fmaxf(mr[mi][1], mt1);
            cc[mi][0] = __expf(mr[mi][0] - mn[mi][0]);
            cc[mi][1] = __expf(mr[mi][1] - mn[mi][1]);
            mr[mi][0] = mn[mi][0];
            mr[mi][1] = mn[mi][1];
#pragma unroll
            for (int nj = 0; nj < 8; ++nj) {
                ctx[mi][nj][0] *= cc[mi][0]; ctx[mi][nj][1] *= cc[mi][0];
                ctx[mi][nj][2] *= cc[mi][1]; ctx[mi][nj][3] *= cc[mi][1];
            }
        }

        // ---- P = exp(S - m) (fp16) + P (Vhi + Vlo), shared V fragments ----
        float sums[2][2] = {{0.0f, 0.0f}, {0.0f, 0.0f}};
#pragma unroll
        for (int kk = 0; kk < 4; ++kk) {
            uint32_t ah[2][4];
#pragma unroll
            for (int mi = 0; mi < 2; ++mi) {
#pragma unroll
                for (int t2 = 0; t2 < 2; ++t2) {
                    const int nj = 2 * kk + t2;
                    const float p0 = __expf(sacc[mi][nj][0] - mn[mi][0]);
                    const float p1 = __expf(sacc[mi][nj][1] - mn[mi][0]);
                    const float p2 = __expf(sacc[mi][nj][2] - mn[mi][1]);
                    const float p3 = __expf(sacc[mi][nj][3] - mn[mi][1]);
                    sums[mi][0] += p0 + p1; sums[mi][1] += p2 + p3;
                    ah[mi][2 * t2 + 0] = pack_h2(p0, p1);
                    ah[mi][2 * t2 + 1] = pack_h2(p2, p3);
                }
            }
            uint32_t vh[4][4], vl[4][4];
#pragma unroll
            for (int n2 = 0; n2 < 4; ++n2) {
                const uint32_t off = (uint32_t)(n2 * 16 + lrow) * 128u
                                   + (((uint32_t)kk * 32u + lcol) ^ xr);
                ldsm_x4(vh[n2][0], vh[n2][1], vh[n2][2], vh[n2][3], st + 16384u + off);
                ldsm_x4(vl[n2][0], vl[n2][1], vl[n2][2], vl[n2][3], st + 24576u + off);
            }
#pragma unroll
            for (int mi = 0; mi < 2; ++mi)
#pragma unroll
                for (int nj = 0; nj < 8; ++nj) {
                    const int n2 = nj >> 1, h = nj & 1;
                    mma_f16(ctx[mi][nj], ah[mi], vh[n2][h], vh[n2][h + 2]);
                    mma_f16(ctx[mi][nj], ah[mi], vl[n2][h], vl[n2][h + 2]);
                }
        }
#pragma unroll
        for (int mi = 0; mi < 2; ++mi) {
            float s0 = sums[mi][0], s1 = sums[mi][1];
            s0 += __shfl_xor_sync(0xffffffffu, s0, 1);
            s0 += __shfl_xor_sync(0xffffffffu, s0, 2);
            s1 += __shfl_xor_sync(0xffffffffu, s1, 1);
            s1 += __shfl_xor_sync(0xffffffffu, s1, 2);
            lr[mi][0] = lr[mi][0] * cc[mi][0] + s0;
            lr[mi][1] = lr[mi][1] * cc[mi][1] + s1;
        }

        __syncthreads();
    }

    // ---- epilogue: normalize, write ctx as fp16 into A slot 0 ----
    const int b  = bh >> 4;
    const int hh = bh & 15;
    const int gq = lane >> 2;
    const int tq = lane & 3;
#pragma unroll
    for (int mi = 0; mi < 2; ++mi) {
        const float i0 = 1.0f / lr[mi][0];
        const float i1 = 1.0f / lr[mi][1];
        const int r0 = q0 + wid * 32 + mi * 16 + gq;
        const int r1 = r0 + 8;
#pragma unroll
        for (int nj = 0; nj < 8; ++nj) {
            const int col = hh * 64 + nj * 8 + tq * 2;
            {
                const size_t idx = ((size_t)r0 * BATCH + b) * DMODEL + col;
                *(__half2*)&g_Af[idx] =
                    __floats2half2_rn(ctx[mi][nj][0] * i0, ctx[mi][nj][1] * i0);
            }
            {
                const size_t idx = ((size_t)r1 * BATCH + b) * DMODEL + col;
                *(__half2*)&g_Af[idx] =
                    __floats2half2_rn(ctx[mi][nj][2] * i1, ctx[mi][nj][3] * i1);
            }
        }
    }
}

// ---------------------------------------------------------------------------
// kernel_launch
// order: query, key, value, time_decay, Wq, bq, Wk, bk, Wv, bv, Wo, bo
// ---------------------------------------------------------------------------
extern "C" void kernel_launch(void* const* d_in, const int* in_sizes, int n_in,
                              void* d_out, int out_size)
{
    const float* query      = (const float*)d_in[0];
    const float* key        = (const float*)d_in[1];
    const float* value      = (const float*)d_in[2];
    const float* time_decay = (const float*)d_in[3];
    const float* Wq = (const float*)d_in[4];
    const float* bq = (const float*)d_in[5];
    const float* Wk = (const float*)d_in[6];
    const float* bk = (const float*)d_in[7];
    const float* Wv = (const float*)d_in[8];
    const float* bv = (const float*)d_in[9];
    const float* Wo = (const float*)d_in[10];
    const float* bo = (const float*)d_in[11];
    float* out = (float*)d_out;

    cudaFuncSetAttribute(gemm_all, cudaFuncAttributeMaxDynamicSharedMemorySize, GEMM_SMEM_BYTES);
    cudaFuncSetAttribute(attn_mma, cudaFuncAttributeMaxDynamicSharedMemorySize, ATTN_SMEM_BYTES);

    // 1. all conversions (two launches)
    conv_w_all<<<dim3(1024, 4), 256>>>(Wq, Wk, Wv, Wo);
    conv_a_all<<<dim3(8192, 3), 256>>>(query, key, value);

    // 2. fused QKV projections (one launch, grid.z = 3)
    gemm_all<<<dim3(8, 64, 3), 256, GEMM_SMEM_BYTES>>>(bq, bk, bv, nullptr, nullptr, -1);

    // 3. attention (128 q-rows per CTA, 4 warps x 2 M-tiles)
    attn_mma<<<dim3(T_LEN / 128, NBH), 128, ATTN_SMEM_BYTES>>>();

    // 4. output projection (+ time_decay)
    gemm_all<<<dim3(8, 64, 1), 256, GEMM_SMEM_BYTES>>>(bo, nullptr, nullptr, out, time_decay, 3);
}